// round 13
// baseline (speedup 1.0000x reference)
#include <cuda_runtime.h>
#include <cuda_fp16.h>
#include <math.h>
#include <stdint.h>

#define BB   256
#define NN   128
#define DM   256
#define NHH  4
#define HDD  64
#define MR   (BB*NN)

// weight plane offsets (elements) in transposed fp16 weight planes [n][k]
#define WOFF_HA   0u
#define WOFF_SA   786432u
#define WOFF_CT   1572864u
#define WOFF_GATE 1966080u
#define WOFF_TR   2752512u
#define WOFF_ARCH 3538944u
#define WOFF_ARCD 3604480u
#define WOFF_BIL  3670016u
#define WTOT      3735552u

// ---------------- scratch ----------------
__device__ float g_q[MR*DM];      // head Q hi|lo half planes
__device__ float g_k[MR*DM];      // head K hi|lo
__device__ float g_v[MR*DM];      // head V hi|lo
__device__ float g_gate[MR*DM];   // sib Q hi|lo, later G fp32
__device__ float g_tr[MR*DM];     // sib K hi|lo, later U fp32
__device__ float g_bil[MR*DM];    // sib V hi|lo, later T fp32
__device__ float g_arcq[MR*DM];   // fp32 h_head
__device__ float g_arcd[MR*DM];   // fp32 h_dep
__device__ float g_bh[MR];
__device__ float g_bd[MR];
__device__ __half g_hr_h[MR*DM],  g_hr_l[MR*DM];
__device__ __half g_at_h[MR*DM],  g_at_l[MR*DM];   // head attn out
__device__ __half g_hm_h[MR*DM],  g_hm_l[MR*DM];
__device__ __half g_cm_h[MR*DM],  g_cm_l[MR*DM];
__device__ __half g_sb_h[MR*DM],  g_sb_l[MR*DM];
__device__ __half g_cav_h[MR*DM], g_cav_l[MR*DM];
__device__ __half g_qa_h[MR*DM],  g_qa_l[MR*DM];   // sib attn out / arc planes
__device__ __half g_whi[WTOT],    g_wlo[WTOT];

// ---------------- helpers ----------------
__device__ __forceinline__ float gelu_f(float x) {
    return 0.5f * x * (1.0f + erff(x * 0.7071067811865475f));
}
__device__ __forceinline__ float sigmoid_f(float x) {
    return 1.0f / (1.0f + expf(-x));
}
__device__ __forceinline__ void hsplit(float x, __half& h, __half& l) {
    h = __float2half_rn(x);
    l = __float2half_rn(x - __half2float(h));
}
__device__ __forceinline__ void psplit2(float a, float b, uint32_t& hi, uint32_t& lo) {
    __half ha = __float2half_rn(a), hb = __float2half_rn(b);
    __half la = __float2half_rn(a - __half2float(ha));
    __half lb = __float2half_rn(b - __half2float(hb));
    __half2 H = __halves2half2(ha, hb), L = __halves2half2(la, lb);
    hi = *(uint32_t*)&H;
    lo = *(uint32_t*)&L;
}
__device__ __forceinline__ uint32_t smem_u32(const void* p) {
    uint32_t a;
    asm("{ .reg .u64 t; cvta.to.shared.u64 t, %1; cvt.u32.u64 %0, t; }" : "=r"(a) : "l"(p));
    return a;
}
__device__ __forceinline__ void cp16(uint32_t saddr, const void* gaddr) {
    asm volatile("cp.async.cg.shared.global [%0], [%1], 16;" :: "r"(saddr), "l"(gaddr));
}
__device__ __forceinline__ void ldm_x4(uint32_t* r, uint32_t saddr) {
    asm volatile("ldmatrix.sync.aligned.m8n8.x4.shared.b16 {%0,%1,%2,%3}, [%4];"
        : "=r"(r[0]), "=r"(r[1]), "=r"(r[2]), "=r"(r[3]) : "r"(saddr));
}
__device__ __forceinline__ void ldm_x4_t(uint32_t* r, uint32_t saddr) {
    asm volatile("ldmatrix.sync.aligned.m8n8.x4.trans.shared.b16 {%0,%1,%2,%3}, [%4];"
        : "=r"(r[0]), "=r"(r[1]), "=r"(r[2]), "=r"(r[3]) : "r"(saddr));
}
__device__ __forceinline__ void mma_f16(float* c, const uint32_t* a, uint32_t b0, uint32_t b1) {
    asm volatile("mma.sync.aligned.m16n8k16.row.col.f32.f16.f16.f32 "
        "{%0,%1,%2,%3}, {%4,%5,%6,%7}, {%8,%9}, {%0,%1,%2,%3};"
        : "+f"(c[0]), "+f"(c[1]), "+f"(c[2]), "+f"(c[3])
        : "r"(a[0]), "r"(a[1]), "r"(a[2]), "r"(a[3]), "r"(b0), "r"(b1));
}

// ---------------------------------------------------------------------------
// Weight transpose + fp16 hi/lo split: W[k][n] -> plane[n*K + k]
// ---------------------------------------------------------------------------
__global__ void __launch_bounds__(256) wconv_k(
    const float* __restrict__ ha, const float* __restrict__ sa,
    const float* __restrict__ ct, const float* __restrict__ gw,
    const float* __restrict__ tw, const float* __restrict__ ahw,
    const float* __restrict__ adw, const float* __restrict__ bil)
{
    int slot = blockIdx.z;
    const float* src; int K; size_t dst;
    if (slot < 12)      { src = ha + (size_t)slot * 65536;       K = 256;  dst = WOFF_HA   + (size_t)slot * 65536; }
    else if (slot < 24) { src = sa + (size_t)(slot-12) * 65536;  K = 256;  dst = WOFF_SA   + (size_t)(slot-12) * 65536; }
    else if (slot < 27) { src = ct + (size_t)(slot-24) * 131072; K = 512;  dst = WOFF_CT   + (size_t)(slot-24) * 131072; }
    else if (slot < 30) { src = gw + (size_t)(slot-27) * 262144; K = 1024; dst = WOFF_GATE + (size_t)(slot-27) * 262144; }
    else if (slot < 33) { src = tw + (size_t)(slot-30) * 262144; K = 1024; dst = WOFF_TR   + (size_t)(slot-30) * 262144; }
    else if (slot == 33){ src = ahw; K = 256; dst = WOFF_ARCH; }
    else if (slot == 34){ src = adw; K = 256; dst = WOFF_ARCD; }
    else                { src = bil; K = 256; dst = WOFF_BIL; }

    int k0 = blockIdx.y * 32;
    if (k0 >= K) return;
    int n0 = blockIdx.x * 32;
    int tx = threadIdx.x, ty = threadIdx.y;

    __shared__ float tile[32][33];
    #pragma unroll
    for (int i = 0; i < 4; i++)
        tile[ty + 8*i][tx] = src[(size_t)(k0 + ty + 8*i) * 256 + n0 + tx];
    __syncthreads();
    #pragma unroll
    for (int i = 0; i < 4; i++) {
        float v = tile[tx][ty + 8*i];
        __half h, l;
        hsplit(v, h, l);
        size_t o = dst + (size_t)(n0 + ty + 8*i) * K + k0 + tx;
        g_whi[o] = h;
        g_wlo[o] = l;
    }
}

// Hin -> Hr fp32 copy + fp16 hi/lo pair
__global__ void __launch_bounds__(256) split_k(
    const float* __restrict__ X, float* __restrict__ Y,
    __half* __restrict__ H, __half* __restrict__ L)
{
    int i = blockIdx.x * 256 + threadIdx.x;
    float4 v = ((const float4*)X)[i];
    ((float4*)Y)[i] = v;
    __half h0,l0,h1,l1,h2,l2,h3,l3;
    hsplit(v.x, h0, l0); hsplit(v.y, h1, l1);
    hsplit(v.z, h2, l2); hsplit(v.w, h3, l3);
    ((__half2*)H)[i*2]   = __halves2half2(h0, h1);
    ((__half2*)H)[i*2+1] = __halves2half2(h2, h3);
    ((__half2*)L)[i*2]   = __halves2half2(l0, l1);
    ((__half2*)L)[i*2+1] = __halves2half2(l2, l3);
}

// ---------------------------------------------------------------------------
// fp16-split tensor-core GEMM (mma.sync.m16n8k16), 3-mma compensation.
// ---------------------------------------------------------------------------
#define MG_SMEM (2 * 40960)

template<int NSRC>
__device__ __forceinline__ void mma_core(
    const __half* Ah0, const __half* Al0, const __half* Ah1, const __half* Al1,
    const __half* Ah2, const __half* Al2, const __half* Ah3, const __half* Al3,
    const __half* __restrict__ Whi, const __half* __restrict__ Wlo,
    const float* bias, float* C, __half* Chi, __half* Clo,
    int m0, int n0, int act, int wst)
{
    constexpr int K = NSRC * 256;
    constexpr int NCH = K / 32;
    extern __shared__ char smx[];
    const uint32_t sb = smem_u32(smx);
    const int tid = threadIdx.x;
    const int w   = tid >> 5, lane = tid & 31;
    const int wm  = (w >> 2) << 6;
    const int wn  = (w & 3) << 5;
    const int lrow = tid >> 1, lseg = tid & 1;

    float acc[4][4][4];
    #pragma unroll
    for (int a = 0; a < 4; a++)
        #pragma unroll
        for (int b = 0; b < 4; b++)
            #pragma unroll
            for (int c = 0; c < 4; c++) acc[a][b][c] = 0.f;

    auto prefetch = [&](int ch, int st) {
        const __half* ah = Ah0;
        const __half* al = Al0;
        if (NSRC > 1) {
            int s = ch >> 3;
            if (s == 1) { ah = Ah1; al = Al1; }
            if (NSRC > 2 && s == 2) { ah = Ah2; al = Al2; }
            if (NSRC > 3 && s == 3) { ah = Ah3; al = Al3; }
        }
        int kloc = (ch << 5) & 255;
        const __half* gah = ah + (size_t)(m0 + lrow) * 256 + kloc + lseg * 16;
        const __half* gal = al + (size_t)(m0 + lrow) * 256 + kloc + lseg * 16;
        const __half* gbh = Whi + (size_t)(n0 + lrow) * K + (ch << 5) + lseg * 16;
        const __half* gbl = Wlo + (size_t)(n0 + lrow) * K + (ch << 5) + lseg * 16;
        uint32_t sa = sb + st * 40960 + lrow * 80 + lseg * 32;
        cp16(sa,              gah); cp16(sa + 16,         gah + 8);
        cp16(sa + 10240,      gal); cp16(sa + 10240 + 16, gal + 8);
        cp16(sa + 20480,      gbh); cp16(sa + 20480 + 16, gbh + 8);
        cp16(sa + 30720,      gbl); cp16(sa + 30720 + 16, gbl + 8);
        asm volatile("cp.async.commit_group;");
    };

    prefetch(0, 0);
    for (int ch = 0; ch < NCH; ch++) {
        asm volatile("cp.async.wait_group 0;");
        __syncthreads();
        if (ch + 1 < NCH) prefetch(ch + 1, (ch + 1) & 1);

        const uint32_t stB = sb + (ch & 1) * 40960;
        #pragma unroll
        for (int kt = 0; kt < 32; kt += 16) {
            uint32_t ahr[4][4], alr[4][4];
            #pragma unroll
            for (int mt = 0; mt < 4; mt++) {
                int row = wm + mt * 16 + (lane & 15);
                int kc  = kt + ((lane >> 4) << 3);
                uint32_t ad = stB + row * 80 + kc * 2;
                ldm_x4(ahr[mt], ad);
                ldm_x4(alr[mt], ad + 10240);
            }
            #pragma unroll
            for (int ng = 0; ng < 2; ng++) {
                int rn = wn + ng * 16 + ((lane >> 4) << 3) + (lane & 7);
                int kc = kt + (((lane >> 3) & 1) << 3);
                uint32_t bd = stB + 20480 + rn * 80 + kc * 2;
                uint32_t bh[4], bl[4];
                ldm_x4(bh, bd);
                ldm_x4(bl, bd + 10240);
                #pragma unroll
                for (int mt = 0; mt < 4; mt++) {
                    #pragma unroll
                    for (int ns = 0; ns < 2; ns++) {
                        float* c = acc[mt][ng * 2 + ns];
                        mma_f16(c, ahr[mt], bh[2*ns], bh[2*ns+1]);
                        mma_f16(c, alr[mt], bh[2*ns], bh[2*ns+1]);
                        mma_f16(c, ahr[mt], bl[2*ns], bl[2*ns+1]);
                    }
                }
            }
        }
    }

    #pragma unroll
    for (int mt = 0; mt < 4; mt++) {
        int r0 = m0 + wm + mt * 16 + (lane >> 2);
        #pragma unroll
        for (int ni = 0; ni < 4; ni++) {
            int col = n0 + wn + ni * 8 + ((lane & 3) << 1);
            float b0 = bias ? bias[col]     : 0.f;
            float b1 = bias ? bias[col + 1] : 0.f;
            float v0 = acc[mt][ni][0] + b0, v1 = acc[mt][ni][1] + b1;
            float v2 = acc[mt][ni][2] + b0, v3 = acc[mt][ni][3] + b1;
            if (act == 1) { v0 = gelu_f(v0); v1 = gelu_f(v1); v2 = gelu_f(v2); v3 = gelu_f(v3); }
            else if (act == 2) { v0 = sigmoid_f(v0); v1 = sigmoid_f(v1); v2 = sigmoid_f(v2); v3 = sigmoid_f(v3); }
            if (wst & 1) {
                *(float2*)(C + (size_t)r0 * 256 + col)       = make_float2(v0, v1);
                *(float2*)(C + (size_t)(r0 + 8) * 256 + col) = make_float2(v2, v3);
            }
            if (wst & 2) {
                __half h0,l0,h1,l1,h2,l2,h3,l3;
                hsplit(v0, h0, l0); hsplit(v1, h1, l1);
                hsplit(v2, h2, l2); hsplit(v3, h3, l3);
                *(__half2*)(Chi + (size_t)r0 * 256 + col)       = __halves2half2(h0, h1);
                *(__half2*)(Clo + (size_t)r0 * 256 + col)       = __halves2half2(l0, l1);
                *(__half2*)(Chi + (size_t)(r0 + 8) * 256 + col) = __halves2half2(h2, h3);
                *(__half2*)(Clo + (size_t)(r0 + 8) * 256 + col) = __halves2half2(l2, l3);
            }
        }
    }
}

// ---- GEMM wrappers ----
__global__ void __launch_bounds__(256) mg1_k(
    const __half* ah, const __half* al,
    const __half* whi, const __half* wlo, const float* bias,
    float* C, __half* Chi, __half* Clo, int act, int wst)
{
    mma_core<1>(ah,al,0,0,0,0,0,0, whi, wlo, bias, C, Chi, Clo,
                blockIdx.x << 7, blockIdx.y << 7, act, wst);
}

// both head+sib QKV in one launch: grid.y = 12
__global__ void __launch_bounds__(256) mg_qkv2_k(
    const __half* ah, const __half* al,
    const __half* hwh, const __half* hwl, const float* hb,
    const __half* swh, const __half* swl, const float* sbb,
    __half* hQh, __half* hQl, __half* hKh, __half* hKl, __half* hVh, __half* hVl,
    __half* sQh, __half* sQl, __half* sKh, __half* sKl, __half* sVh, __half* sVl)
{
    int u = blockIdx.y >> 1;                  // 0..5
    int n0 = (blockIdx.y & 1) << 7;
    bool head = u < 3;
    int s = head ? u : u - 3;
    const __half* wh = (head ? hwh : swh) + s * 65536;
    const __half* wl = (head ? hwl : swl) + s * 65536;
    const float*  bb = (head ? hb  : sbb) + s * 256;
    __half *Ch, *Cl;
    if (head) { Ch = s==0?hQh:(s==1?hKh:hVh); Cl = s==0?hQl:(s==1?hKl:hVl); }
    else      { Ch = s==0?sQh:(s==1?sKh:sVh); Cl = s==0?sQl:(s==1?sKl:sVl); }
    mma_core<1>(ah,al,0,0,0,0,0,0, wh, wl, bb, nullptr, Ch, Cl,
                blockIdx.x << 7, n0, 0, 2);
}

// head out-proj + sib out-proj + child MLP in one launch: grid.y = 6
__global__ void __launch_bounds__(256) proj3_k(
    const __half* ath, const __half* atl,
    const __half* sah, const __half* sal,
    const __half* hrh, const __half* hrl, const __half* cvh, const __half* cvl,
    const __half* hwoh, const __half* hwol, const float* hob,
    const __half* swoh, const __half* swol, const float* sob,
    const __half* cth, const __half* ctl, const float* ctb,
    __half* hmh, __half* hml, __half* sbh, __half* sbl, __half* cmh, __half* cml)
{
    int u = blockIdx.y >> 1;
    int n0 = (blockIdx.y & 1) << 7;
    if (u == 0)
        mma_core<1>(ath,atl,0,0,0,0,0,0, hwoh, hwol, hob, nullptr, hmh, hml,
                    blockIdx.x << 7, n0, 0, 2);
    else if (u == 1)
        mma_core<1>(sah,sal,0,0,0,0,0,0, swoh, swol, sob, nullptr, sbh, sbl,
                    blockIdx.x << 7, n0, 0, 2);
    else
        mma_core<2>(hrh,hrl,cvh,cvl,0,0,0,0, cth, ctl, ctb, nullptr, cmh, cml,
                    blockIdx.x << 7, n0, 1, 2);
}

// gate(sigmoid)+transform(gelu) fused: grid.y = 4
__global__ void __launch_bounds__(256) mg_gt_k(
    const __half* a0h, const __half* a0l, const __half* a1h, const __half* a1l,
    const __half* a2h, const __half* a2l, const __half* a3h, const __half* a3l,
    const __half* gwh, const __half* gwl, const __half* twh, const __half* twl,
    const float* gb, const float* tbias, float* G, float* U)
{
    int n0 = (blockIdx.y & 1) << 7;
    if (blockIdx.y < 2)
        mma_core<4>(a0h,a0l,a1h,a1l,a2h,a2l,a3h,a3l, gwh, gwl, gb,
                    G, nullptr, nullptr, blockIdx.x << 7, n0, 2, 1);
    else
        mma_core<4>(a0h,a0l,a1h,a1l,a2h,a2l,a3h,a3l, twh, twl, tbias,
                    U, nullptr, nullptr, blockIdx.x << 7, n0, 1, 1);
}

// arc head + dep: grid.y = 4
__global__ void __launch_bounds__(256) mg_arc_k(
    const __half* hrh, const __half* hrl,
    const __half* awh, const __half* awl, const float* ahb,
    const __half* dwh, const __half* dwl, const float* adb,
    float* Aq, __half* qah, __half* qal, float* Ad)
{
    int u = blockIdx.y >> 1;
    int n0 = (blockIdx.y & 1) << 7;
    if (u == 0)
        mma_core<1>(hrh,hrl,0,0,0,0,0,0, awh, awl, ahb, Aq, qah, qal,
                    blockIdx.x << 7, n0, 0, 3);
    else
        mma_core<1>(hrh,hrl,0,0,0,0,0,0, dwh, dwl, adb, Ad, nullptr, nullptr,
                    blockIdx.x << 7, n0, 0, 1);
}

// ---------------------------------------------------------------------------
// Tensor-core flash attention: head (z=0, gathered K/V) + sib (z=1, mask).
// 256 threads = 8 warps x 16 query rows.
// ---------------------------------------------------------------------------
#define ASTR 72
#define PLSZ (128 * ASTR * 2)
#define ATC_SMEM (6 * PLSZ + 1024)

__global__ void __launch_bounds__(256) attnB_k(
    const __half* __restrict__ hQh, const __half* __restrict__ hQl,
    const __half* __restrict__ hKh, const __half* __restrict__ hKl,
    const __half* __restrict__ hVh, const __half* __restrict__ hVl,
    const __half* __restrict__ sQh2, const __half* __restrict__ sQl2,
    const __half* __restrict__ sKh2, const __half* __restrict__ sKl2,
    const __half* __restrict__ sVh2, const __half* __restrict__ sVl2,
    const int* __restrict__ ph, const float* __restrict__ mask,
    __half* __restrict__ hOh, __half* __restrict__ hOl,
    __half* __restrict__ sOh, __half* __restrict__ sOl)
{
    extern __shared__ char smc[];
    __half* sm = (__half*)smc;
    int*    phs = (int*)(smc + 6 * PLSZ);
    float*  msk = (float*)(smc + 6 * PLSZ + 512);

    const int b = blockIdx.x, h = blockIdx.y, mode = blockIdx.z;
    const int t = threadIdx.x;
    const int warp = t >> 5, lane = t & 31;
    const int rowbase = b * NN;
    const uint32_t sb = smem_u32(smc);

    const __half* Qh = mode ? sQh2 : hQh;  const __half* Ql = mode ? sQl2 : hQl;
    const __half* Kh = mode ? sKh2 : hKh;  const __half* Kl = mode ? sKl2 : hKl;
    const __half* Vh = mode ? sVh2 : hVh;  const __half* Vl = mode ? sVl2 : hVl;
    __half* Oh = mode ? sOh : hOh;
    __half* Ol = mode ? sOl : hOl;

    if (t < 128) {
        phs[t] = ph[rowbase + t];
        msk[t] = mask[rowbase + t];
    }
    __syncthreads();

    for (int i = t; i < 1024; i += 256) {
        int row = i >> 3, seg = (i & 7) << 3;
        size_t qoff = (size_t)(rowbase + row) * DM + h * HDD + seg;
        *(uint4*)&sm[row*ASTR + seg]              = *(const uint4*)(Qh + qoff);
        *(uint4*)&sm[128*ASTR + row*ASTR + seg]   = *(const uint4*)(Ql + qoff);
        int src = (mode == 0) ? min(max(phs[row], 0), NN - 1) : row;
        size_t koff = (size_t)(rowbase + src) * DM + h * HDD + seg;
        *(uint4*)&sm[2*128*ASTR + row*ASTR + seg] = *(const uint4*)(Kh + koff);
        *(uint4*)&sm[3*128*ASTR + row*ASTR + seg] = *(const uint4*)(Kl + koff);
        *(uint4*)&sm[4*128*ASTR + row*ASTR + seg] = *(const uint4*)(Vh + koff);
        *(uint4*)&sm[5*128*ASTR + row*ASTR + seg] = *(const uint4*)(Vl + koff);
    }
    __syncthreads();

    const int wm = warp << 4;              // 16 query rows per warp
    float S[16][4];
    #pragma unroll
    for (int g = 0; g < 16; g++)
        #pragma unroll
        for (int c = 0; c < 4; c++) S[g][c] = 0.f;

    // S = Q @ K^T
    #pragma unroll
    for (int kt = 0; kt < 4; kt++) {
        uint32_t ah4[4], al4[4];
        uint32_t ad = sb + ((wm + (lane & 15)) * ASTR + kt*16 + ((lane >> 4) << 3)) * 2;
        ldm_x4(ah4, ad);
        ldm_x4(al4, ad + PLSZ);
        #pragma unroll
        for (int ng = 0; ng < 8; ng++) {
            int rn = ng*16 + ((lane >> 4) << 3) + (lane & 7);
            int kc = kt*16 + (((lane >> 3) & 1) << 3);
            uint32_t bd = sb + 2*PLSZ + (rn * ASTR + kc) * 2;
            uint32_t bh4[4], bl4[4];
            ldm_x4(bh4, bd);
            ldm_x4(bl4, bd + PLSZ);
            #pragma unroll
            for (int ns = 0; ns < 2; ns++) {
                float* c = S[ng*2 + ns];
                mma_f16(c, ah4, bh4[2*ns], bh4[2*ns+1]);
                mma_f16(c, al4, bh4[2*ns], bh4[2*ns+1]);
                mma_f16(c, ah4, bl4[2*ns], bl4[2*ns+1]);
            }
        }
    }

    // scale + mask + row max
    float rmax[2] = {-3.4e38f, -3.4e38f};
    #pragma unroll
    for (int ng = 0; ng < 16; ng++)
        #pragma unroll
        for (int c = 0; c < 4; c++) {
            float v = S[ng][c] * 0.125f;
            if (mode == 1) {
                int row = wm + (lane >> 2) + ((c >> 1) << 3);
                int col = (ng << 3) + ((lane & 3) << 1) + (c & 1);
                bool sib = (phs[col] == phs[row]) && (col != row)
                           && (msk[col] > 0.f) && (msk[row] > 0.f);
                if (!sib) v = -1e9f;
            }
            S[ng][c] = v;
            rmax[c >> 1] = fmaxf(rmax[c >> 1], v);
        }
    #pragma unroll
    for (int i = 0; i < 2; i++) {
        rmax[i] = fmaxf(rmax[i], __shfl_xor_sync(0xffffffffu, rmax[i], 1));
        rmax[i] = fmaxf(rmax[i], __shfl_xor_sync(0xffffffffu, rmax[i], 2));
    }

    // exp + row sum
    float rsum[2] = {0.f, 0.f};
    #pragma unroll
    for (int ng = 0; ng < 16; ng++)
        #pragma unroll
        for (int c = 0; c < 4; c++) {
            float e = __expf(S[ng][c] - rmax[c >> 1]);
            S[ng][c] = e;
            rsum[c >> 1] += e;
        }
    #pragma unroll
    for (int i = 0; i < 2; i++) {
        rsum[i] += __shfl_xor_sync(0xffffffffu, rsum[i], 1);
        rsum[i] += __shfl_xor_sync(0xffffffffu, rsum[i], 2);
    }
    float inv0 = 1.f / rsum[0], inv1 = 1.f / rsum[1];

    // O = P @ V (V via ldmatrix.trans)
    float Oa[8][4];
    #pragma unroll
    for (int g = 0; g < 8; g++)
        #pragma unroll
        for (int c = 0; c < 4; c++) Oa[g][c] = 0.f;

    #pragma unroll
    for (int j = 0; j < 8; j++) {
        uint32_t pph[4], ppl[4];
        psplit2(S[2*j][0],   S[2*j][1],   pph[0], ppl[0]);
        psplit2(S[2*j][2],   S[2*j][3],   pph[1], ppl[1]);
        psplit2(S[2*j+1][0], S[2*j+1][1], pph[2], ppl[2]);
        psplit2(S[2*j+1][2], S[2*j+1][3], pph[3], ppl[3]);
        #pragma unroll
        for (int ng = 0; ng < 4; ng++) {
            int kr = (j << 4) + (lane & 15);
            int nc = (ng << 4) + ((lane >> 4) << 3);
            uint32_t bd = sb + 4*PLSZ + (kr * ASTR + nc) * 2;
            uint32_t bvh[4], bvl[4];
            ldm_x4_t(bvh, bd);
            ldm_x4_t(bvl, bd + PLSZ);
            #pragma unroll
            for (int ns = 0; ns < 2; ns++) {
                float* c = Oa[ng*2 + ns];
                mma_f16(c, pph, bvh[2*ns], bvh[2*ns+1]);
                mma_f16(c, ppl, bvh[2*ns], bvh[2*ns+1]);
                mma_f16(c, pph, bvl[2*ns], bvl[2*ns+1]);
            }
        }
    }

    // epilogue
    #pragma unroll
    for (int ng = 0; ng < 8; ng++) {
        int col = h * HDD + (ng << 3) + ((lane & 3) << 1);
        int r0 = rowbase + wm + (lane >> 2);
        float v0 = Oa[ng][0] * inv0, v1 = Oa[ng][1] * inv0;
        float v2 = Oa[ng][2] * inv1, v3 = Oa[ng][3] * inv1;
        __half h0,l0,h1,l1,h2,l2,h3,l3;
        hsplit(v0, h0, l0); hsplit(v1, h1, l1);
        hsplit(v2, h2, l2); hsplit(v3, h3, l3);
        *(__half2*)(Oh + (size_t)r0 * DM + col)       = __halves2half2(h0, h1);
        *(__half2*)(Ol + (size_t)r0 * DM + col)       = __halves2half2(l0, l1);
        *(__half2*)(Oh + (size_t)(r0 + 8) * DM + col) = __halves2half2(h2, h3);
        *(__half2*)(Ol + (size_t)(r0 + 8) * DM + col) = __halves2half2(l2, l3);
    }
}

// ---------------------------------------------------------------------------
// Child scatter-mean (atomic-free); outputs fp16 pair.
// ---------------------------------------------------------------------------
#define CHILD_SMEM (128 * 128 * 4)

__global__ void __launch_bounds__(128) child_k(
    const float* __restrict__ Hr, const int* __restrict__ ph,
    const float* __restrict__ mask,
    __half* __restrict__ Oh, __half* __restrict__ Ol)
{
    extern __shared__ float sm[];
    __shared__ int   phs[128];
    __shared__ float msk[128], inv[128];
    const int b = blockIdx.x, t = threadIdx.x;
    const int d0 = blockIdx.y << 7;

    phs[t] = min(max(ph[b * 128 + t], 0), 127);
    msk[t] = mask[b * 128 + t];
    for (int i = t; i < 16384; i += 128) sm[i] = 0.f;
    __syncthreads();

    float c = 0.f;
    #pragma unroll 4
    for (int n = 0; n < 128; n++) c += (phs[n] == t) ? msk[n] : 0.f;
    inv[t] = 1.f / fmaxf(c, 1.f);

    #pragma unroll 4
    for (int n = 0; n < 128; n++) {
        int hrow = phs[n];
        sm[(hrow << 7) + t] += Hr[(size_t)(b * 128 + n) * 256 + d0 + t];
    }
    __syncthreads();

    for (int hh = 0; hh < 128; hh++) {
        float v = sm[(hh << 7) + t] * inv[hh];
        __half hb, lb;
        hsplit(v, hb, lb);
        size_t o = (size_t)(b * 128 + hh) * 256 + d0 + t;
        Oh[o] = hb;
        Ol[o] = lb;
    }
}

// ---------------------------------------------------------------------------
// Fused gate*update + residual + LayerNorm: warp per row, 8 rows per block.
// ---------------------------------------------------------------------------
__global__ void __launch_bounds__(256) fuse_ln_k(
    float* __restrict__ Hr, const float* __restrict__ g, const float* __restrict__ u,
    const float* __restrict__ lg, const float* __restrict__ lb,
    __half* __restrict__ Hh, __half* __restrict__ Hl)
{
    int row  = blockIdx.x * 8 + (threadIdx.x >> 5);
    int lane = threadIdx.x & 31;
    size_t base = (size_t)row * 256;
    float x[8];
    float s = 0.f, qq = 0.f;
    #pragma unroll
    for (int i = 0; i < 8; i++) {
        int d = lane + (i << 5);
        float v = Hr[base + d] + g[base + d] * u[base + d];
        x[i] = v; s += v; qq += v * v;
    }
    #pragma unroll
    for (int o = 16; o; o >>= 1) {
        s  += __shfl_xor_sync(0xffffffffu, s, o);
        qq += __shfl_xor_sync(0xffffffffu, qq, o);
    }
    float mu = s * (1.f / 256.f);
    float var = fmaxf(qq * (1.f / 256.f) - mu * mu, 0.f);
    float inv = rsqrtf(var + 1e-5f);
    #pragma unroll
    for (int i = 0; i < 8; i++) {
        int d = lane + (i << 5);
        float y = (x[i] - mu) * inv * lg[d] + lb[d];
        Hr[base + d] = y;
        __half hb, lbv;
        hsplit(y, hb, lbv);
        Hh[base + d] = hb;
        Hl[base + d] = lbv;
    }
}

// ---------------------------------------------------------------------------
// both bias vectors in one launch: grid (MR/8, 2)
// ---------------------------------------------------------------------------
__global__ void __launch_bounds__(256) biasvec2_k(
    const float* __restrict__ X0, const float* __restrict__ w0, const float* __restrict__ c0,
    const float* __restrict__ X1, const float* __restrict__ w1, const float* __restrict__ c1,
    float* __restrict__ o0, float* __restrict__ o1)
{
    int sel = blockIdx.y;
    const float* X = sel ? X1 : X0;
    const float* w = sel ? w1 : w0;
    const float* cb = sel ? c1 : c0;
    float* out = sel ? o1 : o0;
    int row  = blockIdx.x * 8 + (threadIdx.x >> 5);
    int lane = threadIdx.x & 31;
    const float* x = X + (size_t)row * 256;
    float s = 0.f;
    for (int d = lane; d < 256; d += 32) s += x[d] * w[d];
    #pragma unroll
    for (int o = 16; o; o >>= 1) s += __shfl_xor_sync(0xffffffffu, s, o);
    if (lane == 0) out[row] = s + cb[0];
}

// ---------------------------------------------------------------------------
// Final scores (fp32 f32x2 path)
// ---------------------------------------------------------------------------
__device__ __forceinline__ void unpk(unsigned long long p, float& x, float& y) {
    asm("mov.b64 {%0, %1}, %2;" : "=f"(x), "=f"(y) : "l"(p));
}
#define SSM_BYTES ((16*132 * 2) * 4)

__global__ void __launch_bounds__(256, 2) scores2_k(
    const float* __restrict__ T, const float* __restrict__ Hd,
    const float* __restrict__ bh, const float* __restrict__ bd,
    float* __restrict__ S)
{
    extern __shared__ float smx2[];
    float* As = smx2;
    float* Bs = smx2 + 16 * 132;
    const int b = blockIdx.x;
    const int tid = threadIdx.x;
    const int tr = tid >> 4, tc = tid & 15;
    const int ra = tid >> 2, ca = (tid & 3) << 2;
    const float* Ab = T  + (size_t)b * NN * DM;
    const float* Bb = Hd + (size_t)b * NN * DM;

    unsigned long long acc[8][4];
    #pragma unroll
    for (int i = 0; i < 8; i++)
        #pragma unroll
        for (int j = 0; j < 4; j++) acc[i][j] = 0ull;

    float4 a0, a1, b0, b1;
    a0 = *(const float4*)(Ab + (size_t)ra * 256 + ca);
    a1 = *(const float4*)(Ab + (size_t)(ra + 64) * 256 + ca);
    b0 = *(const float4*)(Bb + (size_t)ra * 256 + ca);
    b1 = *(const float4*)(Bb + (size_t)(ra + 64) * 256 + ca);

    for (int kt = 0; kt < 256; kt += 16) {
        __syncthreads();
        As[(ca+0)*132 + ra] = a0.x; As[(ca+1)*132 + ra] = a0.y;
        As[(ca+2)*132 + ra] = a0.z; As[(ca+3)*132 + ra] = a0.w;
        As[(ca+0)*132 + ra + 64] = a1.x; As[(ca+1)*132 + ra + 64] = a1.y;
        As[(ca+2)*132 + ra + 64] = a1.z; As[(ca+3)*132 + ra + 64] = a1.w;
        Bs[(ca+0)*132 + ra] = b0.x; Bs[(ca+1)*132 + ra] = b0.y;
        Bs[(ca+2)*132 + ra] = b0.z; Bs[(ca+3)*132 + ra] = b0.w;
        Bs[(ca+0)*132 + ra + 64] = b1.x; Bs[(ca+1)*132 + ra + 64] = b1.y;
        Bs[(ca+2)*132 + ra + 64] = b1.z; Bs[(ca+3)*132 + ra + 64] = b1.w;
        __syncthreads();
        if (kt + 16 < 256) {
            a0 = *(const float4*)(Ab + (size_t)ra * 256 + kt + 16 + ca);
            a1 = *(const float4*)(Ab + (size_t)(ra + 64) * 256 + kt + 16 + ca);
            b0 = *(const float4*)(Bb + (size_t)ra * 256 + kt + 16 + ca);
            b1 = *(const float4*)(Bb + (size_t)(ra + 64) * 256 + kt + 16 + ca);
        }
        #pragma unroll
        for (int kk = 0; kk < 16; kk++) {
            float4 av0 = *(const float4*)&As[kk*132 + (tr << 2)];
            float4 av1 = *(const float4*)&As[kk*132 + 64 + (tr << 2)];
            ulonglong2 bq0 = *(const ulonglong2*)&Bs[kk*132 + (tc << 2)];
            ulonglong2 bq1 = *(const ulonglong2*)&Bs[kk*132 + 64 + (tc << 2)];
            float a_[8] = {av0.x, av0.y, av0.z, av0.w, av1.x, av1.y, av1.z, av1.w};
            #pragma unroll
            for (int i = 0; i < 8; i++) {
                unsigned long long ap;
                asm("mov.b64 %0, {%1, %1};" : "=l"(ap) : "f"(a_[i]));
                asm("fma.rn.f32x2 %0, %1, %2, %0;" : "+l"(acc[i][0]) : "l"(ap), "l"(bq0.x));
                asm("fma.rn.f32x2 %0, %1, %2, %0;" : "+l"(acc[i][1]) : "l"(ap), "l"(bq0.y));
                asm("fma.rn.f32x2 %0, %1, %2, %0;" : "+l"(acc[i][2]) : "l"(ap), "l"(bq1.x));
                asm("fma.rn.f32x2 %0, %1, %2, %0;" : "+l"(acc[i][3]) : "l"(ap), "l"(bq1.y));
            }
        }
    }

    float cb[8];
    #pragma unroll
    for (int j = 0; j < 8; j++) {
        int c = (j < 4) ? ((tc << 2) + j) : (64 + (tc << 2) + j - 4);
        cb[j] = bh[b * NN + c];
    }
    #pragma unroll
    for (int i = 0; i < 8; i++) {
        int n = (i < 4) ? ((tr << 2) + i) : (64 + (tr << 2) + i - 4);
        float rb = bd[b * NN + n];
        float o[8];
        unpk(acc[i][0], o[0], o[1]); unpk(acc[i][1], o[2], o[3]);
        unpk(acc[i][2], o[4], o[5]); unpk(acc[i][3], o[6], o[7]);
        float4 s0 = {o[0]+rb+cb[0], o[1]+rb+cb[1], o[2]+rb+cb[2], o[3]+rb+cb[3]};
        float4 s1 = {o[4]+rb+cb[4], o[5]+rb+cb[5], o[6]+rb+cb[6], o[7]+rb+cb[7]};
        *(float4*)(S + (size_t)b * NN * NN + (size_t)n * NN + (tc << 2))      = s0;
        *(float4*)(S + (size_t)b * NN * NN + (size_t)n * NN + 64 + (tc << 2)) = s1;
    }
}

// ---------------------------------------------------------------------------
// Host orchestration
// ---------------------------------------------------------------------------
extern "C" void kernel_launch(void* const* d_in, const int* in_sizes, int n_in,
                              void* d_out, int out_size)
{
    const float* Hin    = (const float*)d_in[0];
    const int*   ph     = (const int*)  d_in[1];
    const float* mask   = (const float*)d_in[2];
    const float* ha_w   = (const float*)d_in[3];
    const float* ha_b   = (const float*)d_in[4];
    const float* sa_w   = (const float*)d_in[5];
    const float* sa_b   = (const float*)d_in[6];
    const float* ct_w   = (const float*)d_in[7];
    const float* ct_b   = (const float*)d_in[8];
    const float* gate_w = (const float*)d_in[9];
    const float* gate_b = (const float*)d_in[10];
    const float* tr_w   = (const float*)d_in[11];
    const float* tr_b   = (const float*)d_in[12];
    const float* ln_g   = (const float*)d_in[13];
    const float* ln_b   = (const float*)d_in[14];
    const float* ahw    = (const float*)d_in[15];
    const float* ahb    = (const float*)d_in[16];
    const float* adw    = (const float*)d_in[17];
    const float* adb    = (const float*)d_in[18];
    const float* bil    = (const float*)d_in[19];
    const float* bhw    = (const float*)d_in[20];
    const float* bhb    = (const float*)d_in[21];
    const float* bdw    = (const float*)d_in[22];
    const float* bdb    = (const float*)d_in[23];

    float* Hr     = (float*)d_out;
    float* scores = Hr + (size_t)MR * DM;

    float *qf_, *kf_, *vf_, *ga_, *tu_, *bt_, *aq_, *ad_, *bhv_, *bdv_;
    __half *hrh, *hrl, *ath, *atl, *hmh, *hml, *cmh, *cml, *sbh, *sbl,
           *cvh, *cvl, *qah, *qal, *whi_, *wlo_;
    cudaGetSymbolAddress((void**)&qf_, g_q);
    cudaGetSymbolAddress((void**)&kf_, g_k);
    cudaGetSymbolAddress((void**)&vf_, g_v);
    cudaGetSymbolAddress((void**)&ga_, g_gate);
    cudaGetSymbolAddress((void**)&tu_, g_tr);
    cudaGetSymbolAddress((void**)&bt_, g_bil);
    cudaGetSymbolAddress((void**)&aq_, g_arcq);
    cudaGetSymbolAddress((void**)&ad_, g_arcd);
    cudaGetSymbolAddress((void**)&bhv_, g_bh);
    cudaGetSymbolAddress((void**)&bdv_, g_bd);
    cudaGetSymbolAddress((void**)&hrh, g_hr_h);  cudaGetSymbolAddress((void**)&hrl, g_hr_l);
    cudaGetSymbolAddress((void**)&ath, g_at_h);  cudaGetSymbolAddress((void**)&atl, g_at_l);
    cudaGetSymbolAddress((void**)&hmh, g_hm_h);  cudaGetSymbolAddress((void**)&hml, g_hm_l);
    cudaGetSymbolAddress((void**)&cmh, g_cm_h);  cudaGetSymbolAddress((void**)&cml, g_cm_l);
    cudaGetSymbolAddress((void**)&sbh, g_sb_h);  cudaGetSymbolAddress((void**)&sbl, g_sb_l);
    cudaGetSymbolAddress((void**)&cvh, g_cav_h); cudaGetSymbolAddress((void**)&cvl, g_cav_l);
    cudaGetSymbolAddress((void**)&qah, g_qa_h);  cudaGetSymbolAddress((void**)&qal, g_qa_l);
    cudaGetSymbolAddress((void**)&whi_, g_whi);  cudaGetSymbolAddress((void**)&wlo_, g_wlo);

    // half plane views: hi plane then lo plane inside each fp32 scratch array
    __half* hQh = (__half*)qf_; __half* hQl = hQh + (size_t)MR * DM;
    __half* hKh = (__half*)kf_; __half* hKl = hKh + (size_t)MR * DM;
    __half* hVh = (__half*)vf_; __half* hVl = hVh + (size_t)MR * DM;
    __half* sQh = (__half*)ga_; __half* sQl = sQh + (size_t)MR * DM;
    __half* sKh = (__half*)tu_; __half* sKl = sKh + (size_t)MR * DM;
    __half* sVh = (__half*)bt_; __half* sVl = sVh + (size_t)MR * DM;

    cudaFuncSetAttribute(mg1_k,     cudaFuncAttributeMaxDynamicSharedMemorySize, MG_SMEM);
    cudaFuncSetAttribute(mg_qkv2_k, cudaFuncAttributeMaxDynamicSharedMemorySize, MG_SMEM);
    cudaFuncSetAttribute(proj3_k,   cudaFuncAttributeMaxDynamicSharedMemorySize, MG_SMEM);
    cudaFuncSetAttribute(mg_gt_k,   cudaFuncAttributeMaxDynamicSharedMemorySize, MG_SMEM);
    cudaFuncSetAttribute(mg_arc_k,  cudaFuncAttributeMaxDynamicSharedMemorySize, MG_SMEM);
    cudaFuncSetAttribute(attnB_k,   cudaFuncAttributeMaxDynamicSharedMemorySize, ATC_SMEM);
    cudaFuncSetAttribute(child_k,   cudaFuncAttributeMaxDynamicSharedMemorySize, CHILD_SMEM);

    wconv_k<<<dim3(8, 32, 36), dim3(32, 8)>>>(ha_w, sa_w, ct_w, gate_w, tr_w, ahw, adw, bil);
    split_k<<<MR * DM / 1024, 256>>>(Hin, Hr, hrh, hrl);

    for (int i = 0; i < 3; i++) {
        const __half* hwh = whi_ + WOFF_HA + (size_t)i * 4 * 65536;
        const __half* hwl = wlo_ + WOFF_HA + (size_t)i * 4 * 65536;
        const __half* swh = whi_ + WOFF_SA + (size_t)i * 4 * 65536;
        const __half* swl = wlo_ + WOFF_SA + (size_t)i * 4 * 65536;
        const float*  hb  = ha_b + (size_t)i * 1024;
        const float*  sbb = sa_b + (size_t)i * 1024;

        // both QKV sets in one launch
        mg_qkv2_k<<<dim3(256, 12), 256, MG_SMEM>>>(hrh, hrl, hwh, hwl, hb, swh, swl, sbb,
                                                   hQh, hQl, hKh, hKl, hVh, hVl,
                                                   sQh, sQl, sKh, sKl, sVh, sVl);
        // child scatter-mean (independent)
        child_k<<<dim3(256, 2), 128, CHILD_SMEM>>>(Hr, ph, mask, cvh, cvl);
        // both attentions in one launch
        attnB_k<<<dim3(BB, NHH, 2), 256, ATC_SMEM>>>(hQh, hQl, hKh, hKl, hVh, hVl,
                                                     sQh, sQl, sKh, sKl, sVh, sVl,
                                                     ph, mask, ath, atl, qah, qal);
        // head proj + sib proj + child MLP in one launch
        proj3_k<<<dim3(256, 6), 256, MG_SMEM>>>(ath, atl, qah, qal, hrh, hrl, cvh, cvl,
                                                hwh + 3*65536, hwl + 3*65536, hb + 768,
                                                swh + 3*65536, swl + 3*65536, sbb + 768,
                                                whi_ + WOFF_CT + (size_t)i * 131072,
                                                wlo_ + WOFF_CT + (size_t)i * 131072,
                                                ct_b + (size_t)i * 256,
                                                hmh, hml, sbh, sbl, cmh, cml);
        // gated fuse (overwrites g_gate/g_tr fp32 after sib QKV consumed)
        mg_gt_k<<<dim3(256, 4), 256, MG_SMEM>>>(hrh, hrl, hmh, hml, cmh, cml, sbh, sbl,
                                                whi_ + WOFF_GATE + (size_t)i * 262144,
                                                wlo_ + WOFF_GATE + (size_t)i * 262144,
                                                whi_ + WOFF_TR + (size_t)i * 262144,
                                                wlo_ + WOFF_TR + (size_t)i * 262144,
                                                gate_b + (size_t)i * 256,
                                                tr_b   + (size_t)i * 256, ga_, tu_);
        fuse_ln_k<<<MR / 8, 256>>>(Hr, ga_, tu_, ln_g + (size_t)i * 256,
                                   ln_b + (size_t)i * 256, hrh, hrl);
    }

    // final biaffine scorer
    mg_arc_k<<<dim3(256, 4), 256, MG_SMEM>>>(hrh, hrl,
                                             whi_ + WOFF_ARCH, wlo_ + WOFF_ARCH, ahb,
                                             whi_ + WOFF_ARCD, wlo_ + WOFF_ARCD, adb,
                                             aq_, qah, qal, ad_);
    mg1_k<<<dim3(256, 2), 256, MG_SMEM>>>(qah, qal, whi_ + WOFF_BIL, wlo_ + WOFF_BIL,
                                          nullptr, bt_, nullptr, nullptr, 0, 1);
    biasvec2_k<<<dim3(MR / 8, 2), 256>>>(aq_, bhw, bhb, ad_, bdw, bdb, bhv_, bdv_);
    scores2_k<<<BB, 256, SSM_BYTES>>>(bt_, ad_, bhv_, bdv_, scores);
}

// round 14
// speedup vs baseline: 1.1604x; 1.1604x over previous
#include <cuda_runtime.h>
#include <cuda_fp16.h>
#include <math.h>
#include <stdint.h>

#define BB   256
#define NN   128
#define DM   256
#define NHH  4
#define HDD  64
#define MR   (BB*NN)

// weight plane offsets (elements) in transposed fp16 weight planes [n][k]
#define WOFF_HA   0u
#define WOFF_SA   786432u
#define WOFF_CT   1572864u
#define WOFF_GATE 1966080u
#define WOFF_TR   2752512u
#define WOFF_ARCH 3538944u
#define WOFF_ARCD 3604480u
#define WOFF_BIL  3670016u
#define WTOT      3735552u

// ---------------- scratch ----------------
__device__ float g_q[MR*DM];      // head Q hi|lo half planes
__device__ float g_k[MR*DM];      // head K hi|lo
__device__ float g_v[MR*DM];      // head V hi|lo
__device__ float g_gate[MR*DM];   // sib Q hi|lo, later G fp32
__device__ float g_tr[MR*DM];     // sib K hi|lo, later U fp32
__device__ float g_bil[MR*DM];    // sib V hi|lo, later T fp32
__device__ float g_arcq[MR*DM];   // fp32 h_head
__device__ float g_arcd[MR*DM];   // fp32 h_dep
__device__ float g_bh[MR];
__device__ float g_bd[MR];
__device__ __half g_hr_h[MR*DM],  g_hr_l[MR*DM];
__device__ __half g_at_h[MR*DM],  g_at_l[MR*DM];   // head attn out
__device__ __half g_hm_h[MR*DM],  g_hm_l[MR*DM];
__device__ __half g_cm_h[MR*DM],  g_cm_l[MR*DM];
__device__ __half g_sb_h[MR*DM],  g_sb_l[MR*DM];
__device__ __half g_cav_h[MR*DM], g_cav_l[MR*DM];
__device__ __half g_qa_h[MR*DM],  g_qa_l[MR*DM];   // sib attn out / arc planes
__device__ __half g_whi[WTOT],    g_wlo[WTOT];

// ---------------- helpers ----------------
__device__ __forceinline__ float gelu_f(float x) {
    return 0.5f * x * (1.0f + erff(x * 0.7071067811865475f));
}
__device__ __forceinline__ float sigmoid_f(float x) {
    return 1.0f / (1.0f + expf(-x));
}
__device__ __forceinline__ void hsplit(float x, __half& h, __half& l) {
    h = __float2half_rn(x);
    l = __float2half_rn(x - __half2float(h));
}
__device__ __forceinline__ void psplit2(float a, float b, uint32_t& hi, uint32_t& lo) {
    __half ha = __float2half_rn(a), hb = __float2half_rn(b);
    __half la = __float2half_rn(a - __half2float(ha));
    __half lb = __float2half_rn(b - __half2float(hb));
    __half2 H = __halves2half2(ha, hb), L = __halves2half2(la, lb);
    hi = *(uint32_t*)&H;
    lo = *(uint32_t*)&L;
}
__device__ __forceinline__ uint32_t smem_u32(const void* p) {
    uint32_t a;
    asm("{ .reg .u64 t; cvta.to.shared.u64 t, %1; cvt.u32.u64 %0, t; }" : "=r"(a) : "l"(p));
    return a;
}
__device__ __forceinline__ void cp16(uint32_t saddr, const void* gaddr) {
    asm volatile("cp.async.cg.shared.global [%0], [%1], 16;" :: "r"(saddr), "l"(gaddr));
}
__device__ __forceinline__ void ldm_x4(uint32_t* r, uint32_t saddr) {
    asm volatile("ldmatrix.sync.aligned.m8n8.x4.shared.b16 {%0,%1,%2,%3}, [%4];"
        : "=r"(r[0]), "=r"(r[1]), "=r"(r[2]), "=r"(r[3]) : "r"(saddr));
}
__device__ __forceinline__ void ldm_x4_t(uint32_t* r, uint32_t saddr) {
    asm volatile("ldmatrix.sync.aligned.m8n8.x4.trans.shared.b16 {%0,%1,%2,%3}, [%4];"
        : "=r"(r[0]), "=r"(r[1]), "=r"(r[2]), "=r"(r[3]) : "r"(saddr));
}
__device__ __forceinline__ void mma_f16(float* c, const uint32_t* a, uint32_t b0, uint32_t b1) {
    asm volatile("mma.sync.aligned.m16n8k16.row.col.f32.f16.f16.f32 "
        "{%0,%1,%2,%3}, {%4,%5,%6,%7}, {%8,%9}, {%0,%1,%2,%3};"
        : "+f"(c[0]), "+f"(c[1]), "+f"(c[2]), "+f"(c[3])
        : "r"(a[0]), "r"(a[1]), "r"(a[2]), "r"(a[3]), "r"(b0), "r"(b1));
}

// ---------------------------------------------------------------------------
// Weight transpose + fp16 hi/lo split: W[k][n] -> plane[n*K + k]
// ---------------------------------------------------------------------------
__global__ void __launch_bounds__(256) wconv_k(
    const float* __restrict__ ha, const float* __restrict__ sa,
    const float* __restrict__ ct, const float* __restrict__ gw,
    const float* __restrict__ tw, const float* __restrict__ ahw,
    const float* __restrict__ adw, const float* __restrict__ bil)
{
    int slot = blockIdx.z;
    const float* src; int K; size_t dst;
    if (slot < 12)      { src = ha + (size_t)slot * 65536;       K = 256;  dst = WOFF_HA   + (size_t)slot * 65536; }
    else if (slot < 24) { src = sa + (size_t)(slot-12) * 65536;  K = 256;  dst = WOFF_SA   + (size_t)(slot-12) * 65536; }
    else if (slot < 27) { src = ct + (size_t)(slot-24) * 131072; K = 512;  dst = WOFF_CT   + (size_t)(slot-24) * 131072; }
    else if (slot < 30) { src = gw + (size_t)(slot-27) * 262144; K = 1024; dst = WOFF_GATE + (size_t)(slot-27) * 262144; }
    else if (slot < 33) { src = tw + (size_t)(slot-30) * 262144; K = 1024; dst = WOFF_TR   + (size_t)(slot-30) * 262144; }
    else if (slot == 33){ src = ahw; K = 256; dst = WOFF_ARCH; }
    else if (slot == 34){ src = adw; K = 256; dst = WOFF_ARCD; }
    else                { src = bil; K = 256; dst = WOFF_BIL; }

    int k0 = blockIdx.y * 32;
    if (k0 >= K) return;
    int n0 = blockIdx.x * 32;
    int tx = threadIdx.x, ty = threadIdx.y;

    __shared__ float tile[32][33];
    #pragma unroll
    for (int i = 0; i < 4; i++)
        tile[ty + 8*i][tx] = src[(size_t)(k0 + ty + 8*i) * 256 + n0 + tx];
    __syncthreads();
    #pragma unroll
    for (int i = 0; i < 4; i++) {
        float v = tile[tx][ty + 8*i];
        __half h, l;
        hsplit(v, h, l);
        size_t o = dst + (size_t)(n0 + ty + 8*i) * K + k0 + tx;
        g_whi[o] = h;
        g_wlo[o] = l;
    }
}

// Hin -> Hr fp32 copy + fp16 hi/lo pair
__global__ void __launch_bounds__(256) split_k(
    const float* __restrict__ X, float* __restrict__ Y,
    __half* __restrict__ H, __half* __restrict__ L)
{
    int i = blockIdx.x * 256 + threadIdx.x;
    float4 v = ((const float4*)X)[i];
    ((float4*)Y)[i] = v;
    __half h0,l0,h1,l1,h2,l2,h3,l3;
    hsplit(v.x, h0, l0); hsplit(v.y, h1, l1);
    hsplit(v.z, h2, l2); hsplit(v.w, h3, l3);
    ((__half2*)H)[i*2]   = __halves2half2(h0, h1);
    ((__half2*)H)[i*2+1] = __halves2half2(h2, h3);
    ((__half2*)L)[i*2]   = __halves2half2(l0, l1);
    ((__half2*)L)[i*2+1] = __halves2half2(l2, l3);
}

// ---------------------------------------------------------------------------
// fp16-split tensor-core GEMM (mma.sync.m16n8k16).
// TERMS=3: Ahi·Bhi + Alo·Bhi + Ahi·Blo (fp32-grade).
// TERMS=2: Ahi·Bhi + Ahi·Blo (A fp16-rounded; used for gate/transform only).
// ---------------------------------------------------------------------------
#define MG_SMEM (2 * 40960)

template<int NSRC, int TERMS>
__device__ __forceinline__ void mma_core(
    const __half* Ah0, const __half* Al0, const __half* Ah1, const __half* Al1,
    const __half* Ah2, const __half* Al2, const __half* Ah3, const __half* Al3,
    const __half* __restrict__ Whi, const __half* __restrict__ Wlo,
    const float* bias, float* C, __half* Chi, __half* Clo,
    int m0, int n0, int act, int wst)
{
    constexpr int K = NSRC * 256;
    constexpr int NCH = K / 32;
    extern __shared__ char smx[];
    const uint32_t sb = smem_u32(smx);
    const int tid = threadIdx.x;
    const int w   = tid >> 5, lane = tid & 31;
    const int wm  = (w >> 2) << 6;
    const int wn  = (w & 3) << 5;
    const int lrow = tid >> 1, lseg = tid & 1;

    float acc[4][4][4];
    #pragma unroll
    for (int a = 0; a < 4; a++)
        #pragma unroll
        for (int b = 0; b < 4; b++)
            #pragma unroll
            for (int c = 0; c < 4; c++) acc[a][b][c] = 0.f;

    auto prefetch = [&](int ch, int st) {
        const __half* ah = Ah0;
        const __half* al = Al0;
        if (NSRC > 1) {
            int s = ch >> 3;
            if (s == 1) { ah = Ah1; al = Al1; }
            if (NSRC > 2 && s == 2) { ah = Ah2; al = Al2; }
            if (NSRC > 3 && s == 3) { ah = Ah3; al = Al3; }
        }
        int kloc = (ch << 5) & 255;
        const __half* gah = ah + (size_t)(m0 + lrow) * 256 + kloc + lseg * 16;
        const __half* gbh = Whi + (size_t)(n0 + lrow) * K + (ch << 5) + lseg * 16;
        const __half* gbl = Wlo + (size_t)(n0 + lrow) * K + (ch << 5) + lseg * 16;
        uint32_t sa = sb + st * 40960 + lrow * 80 + lseg * 32;
        cp16(sa,              gah); cp16(sa + 16,         gah + 8);
        if (TERMS == 3) {
            const __half* gal = al + (size_t)(m0 + lrow) * 256 + kloc + lseg * 16;
            cp16(sa + 10240,      gal); cp16(sa + 10240 + 16, gal + 8);
        }
        cp16(sa + 20480,      gbh); cp16(sa + 20480 + 16, gbh + 8);
        cp16(sa + 30720,      gbl); cp16(sa + 30720 + 16, gbl + 8);
        asm volatile("cp.async.commit_group;");
    };

    prefetch(0, 0);
    for (int ch = 0; ch < NCH; ch++) {
        asm volatile("cp.async.wait_group 0;");
        __syncthreads();
        if (ch + 1 < NCH) prefetch(ch + 1, (ch + 1) & 1);

        const uint32_t stB = sb + (ch & 1) * 40960;
        #pragma unroll
        for (int kt = 0; kt < 32; kt += 16) {
            uint32_t ahr[4][4], alr[4][4];
            #pragma unroll
            for (int mt = 0; mt < 4; mt++) {
                int row = wm + mt * 16 + (lane & 15);
                int kc  = kt + ((lane >> 4) << 3);
                uint32_t ad = stB + row * 80 + kc * 2;
                ldm_x4(ahr[mt], ad);
                if (TERMS == 3) ldm_x4(alr[mt], ad + 10240);
            }
            #pragma unroll
            for (int ng = 0; ng < 2; ng++) {
                int rn = wn + ng * 16 + ((lane >> 4) << 3) + (lane & 7);
                int kc = kt + (((lane >> 3) & 1) << 3);
                uint32_t bd = stB + 20480 + rn * 80 + kc * 2;
                uint32_t bh[4], bl[4];
                ldm_x4(bh, bd);
                ldm_x4(bl, bd + 10240);
                #pragma unroll
                for (int mt = 0; mt < 4; mt++) {
                    #pragma unroll
                    for (int ns = 0; ns < 2; ns++) {
                        float* c = acc[mt][ng * 2 + ns];
                        mma_f16(c, ahr[mt], bh[2*ns], bh[2*ns+1]);
                        if (TERMS == 3) mma_f16(c, alr[mt], bh[2*ns], bh[2*ns+1]);
                        mma_f16(c, ahr[mt], bl[2*ns], bl[2*ns+1]);
                    }
                }
            }
        }
    }

    #pragma unroll
    for (int mt = 0; mt < 4; mt++) {
        int r0 = m0 + wm + mt * 16 + (lane >> 2);
        #pragma unroll
        for (int ni = 0; ni < 4; ni++) {
            int col = n0 + wn + ni * 8 + ((lane & 3) << 1);
            float b0 = bias ? bias[col]     : 0.f;
            float b1 = bias ? bias[col + 1] : 0.f;
            float v0 = acc[mt][ni][0] + b0, v1 = acc[mt][ni][1] + b1;
            float v2 = acc[mt][ni][2] + b0, v3 = acc[mt][ni][3] + b1;
            if (act == 1) { v0 = gelu_f(v0); v1 = gelu_f(v1); v2 = gelu_f(v2); v3 = gelu_f(v3); }
            else if (act == 2) { v0 = sigmoid_f(v0); v1 = sigmoid_f(v1); v2 = sigmoid_f(v2); v3 = sigmoid_f(v3); }
            if (wst & 1) {
                *(float2*)(C + (size_t)r0 * 256 + col)       = make_float2(v0, v1);
                *(float2*)(C + (size_t)(r0 + 8) * 256 + col) = make_float2(v2, v3);
            }
            if (wst & 2) {
                __half h0,l0,h1,l1,h2,l2,h3,l3;
                hsplit(v0, h0, l0); hsplit(v1, h1, l1);
                hsplit(v2, h2, l2); hsplit(v3, h3, l3);
                *(__half2*)(Chi + (size_t)r0 * 256 + col)       = __halves2half2(h0, h1);
                *(__half2*)(Clo + (size_t)r0 * 256 + col)       = __halves2half2(l0, l1);
                *(__half2*)(Chi + (size_t)(r0 + 8) * 256 + col) = __halves2half2(h2, h3);
                *(__half2*)(Clo + (size_t)(r0 + 8) * 256 + col) = __halves2half2(l2, l3);
            }
        }
    }
}

// ---- GEMM wrappers ----
__global__ void __launch_bounds__(256) mg1_k(
    const __half* ah, const __half* al,
    const __half* whi, const __half* wlo, const float* bias,
    float* C, __half* Chi, __half* Clo, int act, int wst)
{
    mma_core<1,3>(ah,al,0,0,0,0,0,0, whi, wlo, bias, C, Chi, Clo,
                  blockIdx.x << 7, blockIdx.y << 7, act, wst);
}

// both head+sib QKV in one launch: grid.y = 12
__global__ void __launch_bounds__(256) mg_qkv2_k(
    const __half* ah, const __half* al,
    const __half* hwh, const __half* hwl, const float* hb,
    const __half* swh, const __half* swl, const float* sbb,
    __half* hQh, __half* hQl, __half* hKh, __half* hKl, __half* hVh, __half* hVl,
    __half* sQh, __half* sQl, __half* sKh, __half* sKl, __half* sVh, __half* sVl)
{
    int u = blockIdx.y >> 1;                  // 0..5
    int n0 = (blockIdx.y & 1) << 7;
    bool head = u < 3;
    int s = head ? u : u - 3;
    const __half* wh = (head ? hwh : swh) + s * 65536;
    const __half* wl = (head ? hwl : swl) + s * 65536;
    const float*  bb = (head ? hb  : sbb) + s * 256;
    __half *Ch, *Cl;
    if (head) { Ch = s==0?hQh:(s==1?hKh:hVh); Cl = s==0?hQl:(s==1?hKl:hVl); }
    else      { Ch = s==0?sQh:(s==1?sKh:sVh); Cl = s==0?sQl:(s==1?sKl:sVl); }
    mma_core<1,3>(ah,al,0,0,0,0,0,0, wh, wl, bb, nullptr, Ch, Cl,
                  blockIdx.x << 7, n0, 0, 2);
}

// head out-proj + sib out-proj + child MLP in one launch: grid.y = 6
__global__ void __launch_bounds__(256) proj3_k(
    const __half* ath, const __half* atl,
    const __half* sah, const __half* sal,
    const __half* hrh, const __half* hrl, const __half* cvh, const __half* cvl,
    const __half* hwoh, const __half* hwol, const float* hob,
    const __half* swoh, const __half* swol, const float* sob,
    const __half* cth, const __half* ctl, const float* ctb,
    __half* hmh, __half* hml, __half* sbh, __half* sbl, __half* cmh, __half* cml)
{
    int u = blockIdx.y >> 1;
    int n0 = (blockIdx.y & 1) << 7;
    if (u == 0)
        mma_core<1,3>(ath,atl,0,0,0,0,0,0, hwoh, hwol, hob, nullptr, hmh, hml,
                      blockIdx.x << 7, n0, 0, 2);
    else if (u == 1)
        mma_core<1,3>(sah,sal,0,0,0,0,0,0, swoh, swol, sob, nullptr, sbh, sbl,
                      blockIdx.x << 7, n0, 0, 2);
    else
        mma_core<2,3>(hrh,hrl,cvh,cvl,0,0,0,0, cth, ctl, ctb, nullptr, cmh, cml,
                      blockIdx.x << 7, n0, 1, 2);
}

// gate(sigmoid)+transform(gelu) fused, 2-TERM compensation: grid.y = 4
__global__ void __launch_bounds__(256) mg_gt_k(
    const __half* a0h, const __half* a0l, const __half* a1h, const __half* a1l,
    const __half* a2h, const __half* a2l, const __half* a3h, const __half* a3l,
    const __half* gwh, const __half* gwl, const __half* twh, const __half* twl,
    const float* gb, const float* tbias, float* G, float* U)
{
    int n0 = (blockIdx.y & 1) << 7;
    if (blockIdx.y < 2)
        mma_core<4,2>(a0h,a0l,a1h,a1l,a2h,a2l,a3h,a3l, gwh, gwl, gb,
                      G, nullptr, nullptr, blockIdx.x << 7, n0, 2, 1);
    else
        mma_core<4,2>(a0h,a0l,a1h,a1l,a2h,a2l,a3h,a3l, twh, twl, tbias,
                      U, nullptr, nullptr, blockIdx.x << 7, n0, 1, 1);
}

// arc head + dep: grid.y = 4
__global__ void __launch_bounds__(256) mg_arc_k(
    const __half* hrh, const __half* hrl,
    const __half* awh, const __half* awl, const float* ahb,
    const __half* dwh, const __half* dwl, const float* adb,
    float* Aq, __half* qah, __half* qal, float* Ad)
{
    int u = blockIdx.y >> 1;
    int n0 = (blockIdx.y & 1) << 7;
    if (u == 0)
        mma_core<1,3>(hrh,hrl,0,0,0,0,0,0, awh, awl, ahb, Aq, qah, qal,
                      blockIdx.x << 7, n0, 0, 3);
    else
        mma_core<1,3>(hrh,hrl,0,0,0,0,0,0, dwh, dwl, adb, Ad, nullptr, nullptr,
                      blockIdx.x << 7, n0, 0, 1);
}

// ---------------------------------------------------------------------------
// Tensor-core flash attention: head (z=0, gathered K/V) + sib (z=1, mask).
// 256 threads = 8 warps x 16 query rows.
// ---------------------------------------------------------------------------
#define ASTR 72
#define PLSZ (128 * ASTR * 2)
#define ATC_SMEM (6 * PLSZ + 1024)

__global__ void __launch_bounds__(256) attnB_k(
    const __half* __restrict__ hQh, const __half* __restrict__ hQl,
    const __half* __restrict__ hKh, const __half* __restrict__ hKl,
    const __half* __restrict__ hVh, const __half* __restrict__ hVl,
    const __half* __restrict__ sQh2, const __half* __restrict__ sQl2,
    const __half* __restrict__ sKh2, const __half* __restrict__ sKl2,
    const __half* __restrict__ sVh2, const __half* __restrict__ sVl2,
    const int* __restrict__ ph, const float* __restrict__ mask,
    __half* __restrict__ hOh, __half* __restrict__ hOl,
    __half* __restrict__ sOh, __half* __restrict__ sOl)
{
    extern __shared__ char smc[];
    __half* sm = (__half*)smc;
    int*    phs = (int*)(smc + 6 * PLSZ);
    float*  msk = (float*)(smc + 6 * PLSZ + 512);

    const int b = blockIdx.x, h = blockIdx.y, mode = blockIdx.z;
    const int t = threadIdx.x;
    const int warp = t >> 5, lane = t & 31;
    const int rowbase = b * NN;
    const uint32_t sb = smem_u32(smc);

    const __half* Qh = mode ? sQh2 : hQh;  const __half* Ql = mode ? sQl2 : hQl;
    const __half* Kh = mode ? sKh2 : hKh;  const __half* Kl = mode ? sKl2 : hKl;
    const __half* Vh = mode ? sVh2 : hVh;  const __half* Vl = mode ? sVl2 : hVl;
    __half* Oh = mode ? sOh : hOh;
    __half* Ol = mode ? sOl : hOl;

    if (t < 128) {
        phs[t] = ph[rowbase + t];
        msk[t] = mask[rowbase + t];
    }
    __syncthreads();

    for (int i = t; i < 1024; i += 256) {
        int row = i >> 3, seg = (i & 7) << 3;
        size_t qoff = (size_t)(rowbase + row) * DM + h * HDD + seg;
        *(uint4*)&sm[row*ASTR + seg]              = *(const uint4*)(Qh + qoff);
        *(uint4*)&sm[128*ASTR + row*ASTR + seg]   = *(const uint4*)(Ql + qoff);
        int src = (mode == 0) ? min(max(phs[row], 0), NN - 1) : row;
        size_t koff = (size_t)(rowbase + src) * DM + h * HDD + seg;
        *(uint4*)&sm[2*128*ASTR + row*ASTR + seg] = *(const uint4*)(Kh + koff);
        *(uint4*)&sm[3*128*ASTR + row*ASTR + seg] = *(const uint4*)(Kl + koff);
        *(uint4*)&sm[4*128*ASTR + row*ASTR + seg] = *(const uint4*)(Vh + koff);
        *(uint4*)&sm[5*128*ASTR + row*ASTR + seg] = *(const uint4*)(Vl + koff);
    }
    __syncthreads();

    const int wm = warp << 4;              // 16 query rows per warp
    float S[16][4];
    #pragma unroll
    for (int g = 0; g < 16; g++)
        #pragma unroll
        for (int c = 0; c < 4; c++) S[g][c] = 0.f;

    // S = Q @ K^T
    #pragma unroll
    for (int kt = 0; kt < 4; kt++) {
        uint32_t ah4[4], al4[4];
        uint32_t ad = sb + ((wm + (lane & 15)) * ASTR + kt*16 + ((lane >> 4) << 3)) * 2;
        ldm_x4(ah4, ad);
        ldm_x4(al4, ad + PLSZ);
        #pragma unroll
        for (int ng = 0; ng < 8; ng++) {
            int rn = ng*16 + ((lane >> 4) << 3) + (lane & 7);
            int kc = kt*16 + (((lane >> 3) & 1) << 3);
            uint32_t bd = sb + 2*PLSZ + (rn * ASTR + kc) * 2;
            uint32_t bh4[4], bl4[4];
            ldm_x4(bh4, bd);
            ldm_x4(bl4, bd + PLSZ);
            #pragma unroll
            for (int ns = 0; ns < 2; ns++) {
                float* c = S[ng*2 + ns];
                mma_f16(c, ah4, bh4[2*ns], bh4[2*ns+1]);
                mma_f16(c, al4, bh4[2*ns], bh4[2*ns+1]);
                mma_f16(c, ah4, bl4[2*ns], bl4[2*ns+1]);
            }
        }
    }

    // scale + mask + row max
    float rmax[2] = {-3.4e38f, -3.4e38f};
    #pragma unroll
    for (int ng = 0; ng < 16; ng++)
        #pragma unroll
        for (int c = 0; c < 4; c++) {
            float v = S[ng][c] * 0.125f;
            if (mode == 1) {
                int row = wm + (lane >> 2) + ((c >> 1) << 3);
                int col = (ng << 3) + ((lane & 3) << 1) + (c & 1);
                bool sib = (phs[col] == phs[row]) && (col != row)
                           && (msk[col] > 0.f) && (msk[row] > 0.f);
                if (!sib) v = -1e9f;
            }
            S[ng][c] = v;
            rmax[c >> 1] = fmaxf(rmax[c >> 1], v);
        }
    #pragma unroll
    for (int i = 0; i < 2; i++) {
        rmax[i] = fmaxf(rmax[i], __shfl_xor_sync(0xffffffffu, rmax[i], 1));
        rmax[i] = fmaxf(rmax[i], __shfl_xor_sync(0xffffffffu, rmax[i], 2));
    }

    // exp + row sum
    float rsum[2] = {0.f, 0.f};
    #pragma unroll
    for (int ng = 0; ng < 16; ng++)
        #pragma unroll
        for (int c = 0; c < 4; c++) {
            float e = __expf(S[ng][c] - rmax[c >> 1]);
            S[ng][c] = e;
            rsum[c >> 1] += e;
        }
    #pragma unroll
    for (int i = 0; i < 2; i++) {
        rsum[i] += __shfl_xor_sync(0xffffffffu, rsum[i], 1);
        rsum[i] += __shfl_xor_sync(0xffffffffu, rsum[i], 2);
    }
    float inv0 = 1.f / rsum[0], inv1 = 1.f / rsum[1];

    // O = P @ V (V via ldmatrix.trans)
    float Oa[8][4];
    #pragma unroll
    for (int g = 0; g < 8; g++)
        #pragma unroll
        for (int c = 0; c < 4; c++) Oa[g][c] = 0.f;

    #pragma unroll
    for (int j = 0; j < 8; j++) {
        uint32_t pph[4], ppl[4];
        psplit2(S[2*j][0],   S[2*j][1],   pph[0], ppl[0]);
        psplit2(S[2*j][2],   S[2*j][3],   pph[1], ppl[1]);
        psplit2(S[2*j+1][0], S[2*j+1][1], pph[2], ppl[2]);
        psplit2(S[2*j+1][2], S[2*j+1][3], pph[3], ppl[3]);
        #pragma unroll
        for (int ng = 0; ng < 4; ng++) {
            int kr = (j << 4) + (lane & 15);
            int nc = (ng << 4) + ((lane >> 4) << 3);
            uint32_t bd = sb + 4*PLSZ + (kr * ASTR + nc) * 2;
            uint32_t bvh[4], bvl[4];
            ldm_x4_t(bvh, bd);
            ldm_x4_t(bvl, bd + PLSZ);
            #pragma unroll
            for (int ns = 0; ns < 2; ns++) {
                float* c = Oa[ng*2 + ns];
                mma_f16(c, pph, bvh[2*ns], bvh[2*ns+1]);
                mma_f16(c, ppl, bvh[2*ns], bvh[2*ns+1]);
                mma_f16(c, pph, bvl[2*ns], bvl[2*ns+1]);
            }
        }
    }

    // epilogue
    #pragma unroll
    for (int ng = 0; ng < 8; ng++) {
        int col = h * HDD + (ng << 3) + ((lane & 3) << 1);
        int r0 = rowbase + wm + (lane >> 2);
        float v0 = Oa[ng][0] * inv0, v1 = Oa[ng][1] * inv0;
        float v2 = Oa[ng][2] * inv1, v3 = Oa[ng][3] * inv1;
        __half h0,l0,h1,l1,h2,l2,h3,l3;
        hsplit(v0, h0, l0); hsplit(v1, h1, l1);
        hsplit(v2, h2, l2); hsplit(v3, h3, l3);
        *(__half2*)(Oh + (size_t)r0 * DM + col)       = __halves2half2(h0, h1);
        *(__half2*)(Ol + (size_t)r0 * DM + col)       = __halves2half2(l0, l1);
        *(__half2*)(Oh + (size_t)(r0 + 8) * DM + col) = __halves2half2(h2, h3);
        *(__half2*)(Ol + (size_t)(r0 + 8) * DM + col) = __halves2half2(l2, l3);
    }
}

// ---------------------------------------------------------------------------
// Child scatter-mean (atomic-free); outputs fp16 pair.
// ---------------------------------------------------------------------------
#define CHILD_SMEM (128 * 128 * 4)

__global__ void __launch_bounds__(128) child_k(
    const float* __restrict__ Hr, const int* __restrict__ ph,
    const float* __restrict__ mask,
    __half* __restrict__ Oh, __half* __restrict__ Ol)
{
    extern __shared__ float sm[];
    __shared__ int   phs[128];
    __shared__ float msk[128], inv[128];
    const int b = blockIdx.x, t = threadIdx.x;
    const int d0 = blockIdx.y << 7;

    phs[t] = min(max(ph[b * 128 + t], 0), 127);
    msk[t] = mask[b * 128 + t];
    for (int i = t; i < 16384; i += 128) sm[i] = 0.f;
    __syncthreads();

    float c = 0.f;
    #pragma unroll 4
    for (int n = 0; n < 128; n++) c += (phs[n] == t) ? msk[n] : 0.f;
    inv[t] = 1.f / fmaxf(c, 1.f);

    #pragma unroll 4
    for (int n = 0; n < 128; n++) {
        int hrow = phs[n];
        sm[(hrow << 7) + t] += Hr[(size_t)(b * 128 + n) * 256 + d0 + t];
    }
    __syncthreads();

    for (int hh = 0; hh < 128; hh++) {
        float v = sm[(hh << 7) + t] * inv[hh];
        __half hb, lb;
        hsplit(v, hb, lb);
        size_t o = (size_t)(b * 128 + hh) * 256 + d0 + t;
        Oh[o] = hb;
        Ol[o] = lb;
    }
}

// ---------------------------------------------------------------------------
// Fused gate*update + residual + LayerNorm: warp per row, 8 rows per block.
// ---------------------------------------------------------------------------
__global__ void __launch_bounds__(256) fuse_ln_k(
    float* __restrict__ Hr, const float* __restrict__ g, const float* __restrict__ u,
    const float* __restrict__ lg, const float* __restrict__ lb,
    __half* __restrict__ Hh, __half* __restrict__ Hl)
{
    int row  = blockIdx.x * 8 + (threadIdx.x >> 5);
    int lane = threadIdx.x & 31;
    size_t base = (size_t)row * 256;
    float x[8];
    float s = 0.f, qq = 0.f;
    #pragma unroll
    for (int i = 0; i < 8; i++) {
        int d = lane + (i << 5);
        float v = Hr[base + d] + g[base + d] * u[base + d];
        x[i] = v; s += v; qq += v * v;
    }
    #pragma unroll
    for (int o = 16; o; o >>= 1) {
        s  += __shfl_xor_sync(0xffffffffu, s, o);
        qq += __shfl_xor_sync(0xffffffffu, qq, o);
    }
    float mu = s * (1.f / 256.f);
    float var = fmaxf(qq * (1.f / 256.f) - mu * mu, 0.f);
    float inv = rsqrtf(var + 1e-5f);
    #pragma unroll
    for (int i = 0; i < 8; i++) {
        int d = lane + (i << 5);
        float y = (x[i] - mu) * inv * lg[d] + lb[d];
        Hr[base + d] = y;
        __half hb, lbv;
        hsplit(y, hb, lbv);
        Hh[base + d] = hb;
        Hl[base + d] = lbv;
    }
}

// ---------------------------------------------------------------------------
// both bias vectors in one launch: grid (MR/8, 2)
// ---------------------------------------------------------------------------
__global__ void __launch_bounds__(256) biasvec2_k(
    const float* __restrict__ X0, const float* __restrict__ w0, const float* __restrict__ c0,
    const float* __restrict__ X1, const float* __restrict__ w1, const float* __restrict__ c1,
    float* __restrict__ o0, float* __restrict__ o1)
{
    int sel = blockIdx.y;
    const float* X = sel ? X1 : X0;
    const float* w = sel ? w1 : w0;
    const float* cb = sel ? c1 : c0;
    float* out = sel ? o1 : o0;
    int row  = blockIdx.x * 8 + (threadIdx.x >> 5);
    int lane = threadIdx.x & 31;
    const float* x = X + (size_t)row * 256;
    float s = 0.f;
    for (int d = lane; d < 256; d += 32) s += x[d] * w[d];
    #pragma unroll
    for (int o = 16; o; o >>= 1) s += __shfl_xor_sync(0xffffffffu, s, o);
    if (lane == 0) out[row] = s + cb[0];
}

// ---------------------------------------------------------------------------
// Final scores (fp32 f32x2 path)
// ---------------------------------------------------------------------------
__device__ __forceinline__ void unpk(unsigned long long p, float& x, float& y) {
    asm("mov.b64 {%0, %1}, %2;" : "=f"(x), "=f"(y) : "l"(p));
}
#define SSM_BYTES ((16*132 * 2) * 4)

__global__ void __launch_bounds__(256, 2) scores2_k(
    const float* __restrict__ T, const float* __restrict__ Hd,
    const float* __restrict__ bh, const float* __restrict__ bd,
    float* __restrict__ S)
{
    extern __shared__ float smx2[];
    float* As = smx2;
    float* Bs = smx2 + 16 * 132;
    const int b = blockIdx.x;
    const int tid = threadIdx.x;
    const int tr = tid >> 4, tc = tid & 15;
    const int ra = tid >> 2, ca = (tid & 3) << 2;
    const float* Ab = T  + (size_t)b * NN * DM;
    const float* Bb = Hd + (size_t)b * NN * DM;

    unsigned long long acc[8][4];
    #pragma unroll
    for (int i = 0; i < 8; i++)
        #pragma unroll
        for (int j = 0; j < 4; j++) acc[i][j] = 0ull;

    float4 a0, a1, b0, b1;
    a0 = *(const float4*)(Ab + (size_t)ra * 256 + ca);
    a1 = *(const float4*)(Ab + (size_t)(ra + 64) * 256 + ca);
    b0 = *(const float4*)(Bb + (size_t)ra * 256 + ca);
    b1 = *(const float4*)(Bb + (size_t)(ra + 64) * 256 + ca);

    for (int kt = 0; kt < 256; kt += 16) {
        __syncthreads();
        As[(ca+0)*132 + ra] = a0.x; As[(ca+1)*132 + ra] = a0.y;
        As[(ca+2)*132 + ra] = a0.z; As[(ca+3)*132 + ra] = a0.w;
        As[(ca+0)*132 + ra + 64] = a1.x; As[(ca+1)*132 + ra + 64] = a1.y;
        As[(ca+2)*132 + ra + 64] = a1.z; As[(ca+3)*132 + ra + 64] = a1.w;
        Bs[(ca+0)*132 + ra] = b0.x; Bs[(ca+1)*132 + ra] = b0.y;
        Bs[(ca+2)*132 + ra] = b0.z; Bs[(ca+3)*132 + ra] = b0.w;
        Bs[(ca+0)*132 + ra + 64] = b1.x; Bs[(ca+1)*132 + ra + 64] = b1.y;
        Bs[(ca+2)*132 + ra + 64] = b1.z; Bs[(ca+3)*132 + ra + 64] = b1.w;
        __syncthreads();
        if (kt + 16 < 256) {
            a0 = *(const float4*)(Ab + (size_t)ra * 256 + kt + 16 + ca);
            a1 = *(const float4*)(Ab + (size_t)(ra + 64) * 256 + kt + 16 + ca);
            b0 = *(const float4*)(Bb + (size_t)ra * 256 + kt + 16 + ca);
            b1 = *(const float4*)(Bb + (size_t)(ra + 64) * 256 + kt + 16 + ca);
        }
        #pragma unroll
        for (int kk = 0; kk < 16; kk++) {
            float4 av0 = *(const float4*)&As[kk*132 + (tr << 2)];
            float4 av1 = *(const float4*)&As[kk*132 + 64 + (tr << 2)];
            ulonglong2 bq0 = *(const ulonglong2*)&Bs[kk*132 + (tc << 2)];
            ulonglong2 bq1 = *(const ulonglong2*)&Bs[kk*132 + 64 + (tc << 2)];
            float a_[8] = {av0.x, av0.y, av0.z, av0.w, av1.x, av1.y, av1.z, av1.w};
            #pragma unroll
            for (int i = 0; i < 8; i++) {
                unsigned long long ap;
                asm("mov.b64 %0, {%1, %1};" : "=l"(ap) : "f"(a_[i]));
                asm("fma.rn.f32x2 %0, %1, %2, %0;" : "+l"(acc[i][0]) : "l"(ap), "l"(bq0.x));
                asm("fma.rn.f32x2 %0, %1, %2, %0;" : "+l"(acc[i][1]) : "l"(ap), "l"(bq0.y));
                asm("fma.rn.f32x2 %0, %1, %2, %0;" : "+l"(acc[i][2]) : "l"(ap), "l"(bq1.x));
                asm("fma.rn.f32x2 %0, %1, %2, %0;" : "+l"(acc[i][3]) : "l"(ap), "l"(bq1.y));
            }
        }
    }

    float cb[8];
    #pragma unroll
    for (int j = 0; j < 8; j++) {
        int c = (j < 4) ? ((tc << 2) + j) : (64 + (tc << 2) + j - 4);
        cb[j] = bh[b * NN + c];
    }
    #pragma unroll
    for (int i = 0; i < 8; i++) {
        int n = (i < 4) ? ((tr << 2) + i) : (64 + (tr << 2) + i - 4);
        float rb = bd[b * NN + n];
        float o[8];
        unpk(acc[i][0], o[0], o[1]); unpk(acc[i][1], o[2], o[3]);
        unpk(acc[i][2], o[4], o[5]); unpk(acc[i][3], o[6], o[7]);
        float4 s0 = {o[0]+rb+cb[0], o[1]+rb+cb[1], o[2]+rb+cb[2], o[3]+rb+cb[3]};
        float4 s1 = {o[4]+rb+cb[4], o[5]+rb+cb[5], o[6]+rb+cb[6], o[7]+rb+cb[7]};
        *(float4*)(S + (size_t)b * NN * NN + (size_t)n * NN + (tc << 2))      = s0;
        *(float4*)(S + (size_t)b * NN * NN + (size_t)n * NN + 64 + (tc << 2)) = s1;
    }
}

// ---------------------------------------------------------------------------
// Host orchestration
// ---------------------------------------------------------------------------
extern "C" void kernel_launch(void* const* d_in, const int* in_sizes, int n_in,
                              void* d_out, int out_size)
{
    const float* Hin    = (const float*)d_in[0];
    const int*   ph     = (const int*)  d_in[1];
    const float* mask   = (const float*)d_in[2];
    const float* ha_w   = (const float*)d_in[3];
    const float* ha_b   = (const float*)d_in[4];
    const float* sa_w   = (const float*)d_in[5];
    const float* sa_b   = (const float*)d_in[6];
    const float* ct_w   = (const float*)d_in[7];
    const float* ct_b   = (const float*)d_in[8];
    const float* gate_w = (const float*)d_in[9];
    const float* gate_b = (const float*)d_in[10];
    const float* tr_w   = (const float*)d_in[11];
    const float* tr_b   = (const float*)d_in[12];
    const float* ln_g   = (const float*)d_in[13];
    const float* ln_b   = (const float*)d_in[14];
    const float* ahw    = (const float*)d_in[15];
    const float* ahb    = (const float*)d_in[16];
    const float* adw    = (const float*)d_in[17];
    const float* adb    = (const float*)d_in[18];
    const float* bil    = (const float*)d_in[19];
    const float* bhw    = (const float*)d_in[20];
    const float* bhb    = (const float*)d_in[21];
    const float* bdw    = (const float*)d_in[22];
    const float* bdb    = (const float*)d_in[23];

    float* Hr     = (float*)d_out;
    float* scores = Hr + (size_t)MR * DM;

    float *qf_, *kf_, *vf_, *ga_, *tu_, *bt_, *aq_, *ad_, *bhv_, *bdv_;
    __half *hrh, *hrl, *ath, *atl, *hmh, *hml, *cmh, *cml, *sbh, *sbl,
           *cvh, *cvl, *qah, *qal, *whi_, *wlo_;
    cudaGetSymbolAddress((void**)&qf_, g_q);
    cudaGetSymbolAddress((void**)&kf_, g_k);
    cudaGetSymbolAddress((void**)&vf_, g_v);
    cudaGetSymbolAddress((void**)&ga_, g_gate);
    cudaGetSymbolAddress((void**)&tu_, g_tr);
    cudaGetSymbolAddress((void**)&bt_, g_bil);
    cudaGetSymbolAddress((void**)&aq_, g_arcq);
    cudaGetSymbolAddress((void**)&ad_, g_arcd);
    cudaGetSymbolAddress((void**)&bhv_, g_bh);
    cudaGetSymbolAddress((void**)&bdv_, g_bd);
    cudaGetSymbolAddress((void**)&hrh, g_hr_h);  cudaGetSymbolAddress((void**)&hrl, g_hr_l);
    cudaGetSymbolAddress((void**)&ath, g_at_h);  cudaGetSymbolAddress((void**)&atl, g_at_l);
    cudaGetSymbolAddress((void**)&hmh, g_hm_h);  cudaGetSymbolAddress((void**)&hml, g_hm_l);
    cudaGetSymbolAddress((void**)&cmh, g_cm_h);  cudaGetSymbolAddress((void**)&cml, g_cm_l);
    cudaGetSymbolAddress((void**)&sbh, g_sb_h);  cudaGetSymbolAddress((void**)&sbl, g_sb_l);
    cudaGetSymbolAddress((void**)&cvh, g_cav_h); cudaGetSymbolAddress((void**)&cvl, g_cav_l);
    cudaGetSymbolAddress((void**)&qah, g_qa_h);  cudaGetSymbolAddress((void**)&qal, g_qa_l);
    cudaGetSymbolAddress((void**)&whi_, g_whi);  cudaGetSymbolAddress((void**)&wlo_, g_wlo);

    // half plane views: hi plane then lo plane inside each fp32 scratch array
    __half* hQh = (__half*)qf_; __half* hQl = hQh + (size_t)MR * DM;
    __half* hKh = (__half*)kf_; __half* hKl = hKh + (size_t)MR * DM;
    __half* hVh = (__half*)vf_; __half* hVl = hVh + (size_t)MR * DM;
    __half* sQh = (__half*)ga_; __half* sQl = sQh + (size_t)MR * DM;
    __half* sKh = (__half*)tu_; __half* sKl = sKh + (size_t)MR * DM;
    __half* sVh = (__half*)bt_; __half* sVl = sVh + (size_t)MR * DM;

    cudaFuncSetAttribute(mg1_k,     cudaFuncAttributeMaxDynamicSharedMemorySize, MG_SMEM);
    cudaFuncSetAttribute(mg_qkv2_k, cudaFuncAttributeMaxDynamicSharedMemorySize, MG_SMEM);
    cudaFuncSetAttribute(proj3_k,   cudaFuncAttributeMaxDynamicSharedMemorySize, MG_SMEM);
    cudaFuncSetAttribute(mg_gt_k,   cudaFuncAttributeMaxDynamicSharedMemorySize, MG_SMEM);
    cudaFuncSetAttribute(mg_arc_k,  cudaFuncAttributeMaxDynamicSharedMemorySize, MG_SMEM);
    cudaFuncSetAttribute(attnB_k,   cudaFuncAttributeMaxDynamicSharedMemorySize, ATC_SMEM);
    cudaFuncSetAttribute(child_k,   cudaFuncAttributeMaxDynamicSharedMemorySize, CHILD_SMEM);

    wconv_k<<<dim3(8, 32, 36), dim3(32, 8)>>>(ha_w, sa_w, ct_w, gate_w, tr_w, ahw, adw, bil);
    split_k<<<MR * DM / 1024, 256>>>(Hin, Hr, hrh, hrl);

    for (int i = 0; i < 3; i++) {
        const __half* hwh = whi_ + WOFF_HA + (size_t)i * 4 * 65536;
        const __half* hwl = wlo_ + WOFF_HA + (size_t)i * 4 * 65536;
        const __half* swh = whi_ + WOFF_SA + (size_t)i * 4 * 65536;
        const __half* swl = wlo_ + WOFF_SA + (size_t)i * 4 * 65536;
        const float*  hb  = ha_b + (size_t)i * 1024;
        const float*  sbb = sa_b + (size_t)i * 1024;

        // both QKV sets in one launch
        mg_qkv2_k<<<dim3(256, 12), 256, MG_SMEM>>>(hrh, hrl, hwh, hwl, hb, swh, swl, sbb,
                                                   hQh, hQl, hKh, hKl, hVh, hVl,
                                                   sQh, sQl, sKh, sKl, sVh, sVl);
        // child scatter-mean (independent)
        child_k<<<dim3(256, 2), 128, CHILD_SMEM>>>(Hr, ph, mask, cvh, cvl);
        // both attentions in one launch
        attnB_k<<<dim3(BB, NHH, 2), 256, ATC_SMEM>>>(hQh, hQl, hKh, hKl, hVh, hVl,
                                                     sQh, sQl, sKh, sKl, sVh, sVl,
                                                     ph, mask, ath, atl, qah, qal);
        // head proj + sib proj + child MLP in one launch
        proj3_k<<<dim3(256, 6), 256, MG_SMEM>>>(ath, atl, qah, qal, hrh, hrl, cvh, cvl,
                                                hwh + 3*65536, hwl + 3*65536, hb + 768,
                                                swh + 3*65536, swl + 3*65536, sbb + 768,
                                                whi_ + WOFF_CT + (size_t)i * 131072,
                                                wlo_ + WOFF_CT + (size_t)i * 131072,
                                                ct_b + (size_t)i * 256,
                                                hmh, hml, sbh, sbl, cmh, cml);
        // gated fuse (2-term compensation — 44% of GEMM flops at 2/3 cost)
        mg_gt_k<<<dim3(256, 4), 256, MG_SMEM>>>(hrh, hrl, hmh, hml, cmh, cml, sbh, sbl,
                                                whi_ + WOFF_GATE + (size_t)i * 262144,
                                                wlo_ + WOFF_GATE + (size_t)i * 262144,
                                                whi_ + WOFF_TR + (size_t)i * 262144,
                                                wlo_ + WOFF_TR + (size_t)i * 262144,
                                                gate_b + (size_t)i * 256,
                                                tr_b   + (size_t)i * 256, ga_, tu_);
        fuse_ln_k<<<MR / 8, 256>>>(Hr, ga_, tu_, ln_g + (size_t)i * 256,
                                   ln_b + (size_t)i * 256, hrh, hrl);
    }

    // final biaffine scorer
    mg_arc_k<<<dim3(256, 4), 256, MG_SMEM>>>(hrh, hrl,
                                             whi_ + WOFF_ARCH, wlo_ + WOFF_ARCH, ahb,
                                             whi_ + WOFF_ARCD, wlo_ + WOFF_ARCD, adb,
                                             aq_, qah, qal, ad_);
    mg1_k<<<dim3(256, 2), 256, MG_SMEM>>>(qah, qal, whi_ + WOFF_BIL, wlo_ + WOFF_BIL,
                                          nullptr, bt_, nullptr, nullptr, 0, 1);
    biasvec2_k<<<dim3(MR / 8, 2), 256>>>(aq_, bhw, bhb, ad_, bdw, bdb, bhv_, bdv_);
    scores2_k<<<BB, 256, SSM_BYTES>>>(bt_, ad_, bhv_, bdv_, scores);
}

// round 15
// speedup vs baseline: 1.4726x; 1.2691x over previous
#include <cuda_runtime.h>
#include <cuda_fp16.h>
#include <math.h>
#include <stdint.h>

#define BB   256
#define NN   128
#define DM   256
#define NHH  4
#define HDD  64
#define MR   (BB*NN)

// weight plane offsets (elements) in transposed fp16 weight planes [n][k]
#define WOFF_HA   0u
#define WOFF_SA   786432u
#define WOFF_CT   1572864u
#define WOFF_GATE 1966080u
#define WOFF_TR   2752512u
#define WOFF_ARCH 3538944u
#define WOFF_ARCD 3604480u
#define WOFF_BIL  3670016u
#define WTOT      3735552u

// ---------------- scratch ----------------
__device__ float g_q[MR*DM];      // head Q hi|lo half planes
__device__ float g_k[MR*DM];      // head K hi|lo
__device__ float g_v[MR*DM];      // head V hi|lo
__device__ float g_gate[MR*DM];   // sib Q hi|lo, later G fp32
__device__ float g_tr[MR*DM];     // sib K hi|lo, later U fp32
__device__ float g_bil[MR*DM];    // sib V hi|lo, later T fp32
__device__ float g_arcq[MR*DM];   // fp32 h_head
__device__ float g_arcd[MR*DM];   // fp32 h_dep
__device__ float g_bh[MR];
__device__ float g_bd[MR];
__device__ __half g_hr_h[MR*DM],  g_hr_l[MR*DM];
__device__ __half g_at_h[MR*DM],  g_at_l[MR*DM];   // head attn out
__device__ __half g_hm_h[MR*DM],  g_hm_l[MR*DM];
__device__ __half g_cm_h[MR*DM],  g_cm_l[MR*DM];
__device__ __half g_sb_h[MR*DM],  g_sb_l[MR*DM];
__device__ __half g_cav_h[MR*DM], g_cav_l[MR*DM];
__device__ __half g_qa_h[MR*DM],  g_qa_l[MR*DM];   // sib attn out / arc planes
__device__ __half g_whi[WTOT],    g_wlo[WTOT];

// ---------------- helpers ----------------
__device__ __forceinline__ float gelu_f(float x) {
    return 0.5f * x * (1.0f + erff(x * 0.7071067811865475f));
}
__device__ __forceinline__ float sigmoid_f(float x) {
    return 1.0f / (1.0f + expf(-x));
}
__device__ __forceinline__ void hsplit(float x, __half& h, __half& l) {
    h = __float2half_rn(x);
    l = __float2half_rn(x - __half2float(h));
}
__device__ __forceinline__ void psplit2(float a, float b, uint32_t& hi, uint32_t& lo) {
    __half ha = __float2half_rn(a), hb = __float2half_rn(b);
    __half la = __float2half_rn(a - __half2float(ha));
    __half lb = __float2half_rn(b - __half2float(hb));
    __half2 H = __halves2half2(ha, hb), L = __halves2half2(la, lb);
    hi = *(uint32_t*)&H;
    lo = *(uint32_t*)&L;
}
__device__ __forceinline__ uint32_t smem_u32(const void* p) {
    uint32_t a;
    asm("{ .reg .u64 t; cvta.to.shared.u64 t, %1; cvt.u32.u64 %0, t; }" : "=r"(a) : "l"(p));
    return a;
}
__device__ __forceinline__ void cp16(uint32_t saddr, const void* gaddr) {
    asm volatile("cp.async.cg.shared.global [%0], [%1], 16;" :: "r"(saddr), "l"(gaddr));
}
__device__ __forceinline__ void ldm_x4(uint32_t* r, uint32_t saddr) {
    asm volatile("ldmatrix.sync.aligned.m8n8.x4.shared.b16 {%0,%1,%2,%3}, [%4];"
        : "=r"(r[0]), "=r"(r[1]), "=r"(r[2]), "=r"(r[3]) : "r"(saddr));
}
__device__ __forceinline__ void ldm_x4_t(uint32_t* r, uint32_t saddr) {
    asm volatile("ldmatrix.sync.aligned.m8n8.x4.trans.shared.b16 {%0,%1,%2,%3}, [%4];"
        : "=r"(r[0]), "=r"(r[1]), "=r"(r[2]), "=r"(r[3]) : "r"(saddr));
}
__device__ __forceinline__ void mma_f16(float* c, const uint32_t* a, uint32_t b0, uint32_t b1) {
    asm volatile("mma.sync.aligned.m16n8k16.row.col.f32.f16.f16.f32 "
        "{%0,%1,%2,%3}, {%4,%5,%6,%7}, {%8,%9}, {%0,%1,%2,%3};"
        : "+f"(c[0]), "+f"(c[1]), "+f"(c[2]), "+f"(c[3])
        : "r"(a[0]), "r"(a[1]), "r"(a[2]), "r"(a[3]), "r"(b0), "r"(b1));
}

// ---------------------------------------------------------------------------
// Weight transpose + fp16 hi/lo split: W[k][n] -> plane[n*K + k]
// ---------------------------------------------------------------------------
__global__ void __launch_bounds__(256) wconv_k(
    const float* __restrict__ ha, const float* __restrict__ sa,
    const float* __restrict__ ct, const float* __restrict__ gw,
    const float* __restrict__ tw, const float* __restrict__ ahw,
    const float* __restrict__ adw, const float* __restrict__ bil)
{
    int slot = blockIdx.z;
    const float* src; int K; size_t dst;
    if (slot < 12)      { src = ha + (size_t)slot * 65536;       K = 256;  dst = WOFF_HA   + (size_t)slot * 65536; }
    else if (slot < 24) { src = sa + (size_t)(slot-12) * 65536;  K = 256;  dst = WOFF_SA   + (size_t)(slot-12) * 65536; }
    else if (slot < 27) { src = ct + (size_t)(slot-24) * 131072; K = 512;  dst = WOFF_CT   + (size_t)(slot-24) * 131072; }
    else if (slot < 30) { src = gw + (size_t)(slot-27) * 262144; K = 1024; dst = WOFF_GATE + (size_t)(slot-27) * 262144; }
    else if (slot < 33) { src = tw + (size_t)(slot-30) * 262144; K = 1024; dst = WOFF_TR   + (size_t)(slot-30) * 262144; }
    else if (slot == 33){ src = ahw; K = 256; dst = WOFF_ARCH; }
    else if (slot == 34){ src = adw; K = 256; dst = WOFF_ARCD; }
    else                { src = bil; K = 256; dst = WOFF_BIL; }

    int k0 = blockIdx.y * 32;
    if (k0 >= K) return;
    int n0 = blockIdx.x * 32;
    int tx = threadIdx.x, ty = threadIdx.y;

    __shared__ float tile[32][33];
    #pragma unroll
    for (int i = 0; i < 4; i++)
        tile[ty + 8*i][tx] = src[(size_t)(k0 + ty + 8*i) * 256 + n0 + tx];
    __syncthreads();
    #pragma unroll
    for (int i = 0; i < 4; i++) {
        float v = tile[tx][ty + 8*i];
        __half h, l;
        hsplit(v, h, l);
        size_t o = dst + (size_t)(n0 + ty + 8*i) * K + k0 + tx;
        g_whi[o] = h;
        g_wlo[o] = l;
    }
}

// Hin -> Hr fp32 copy + fp16 hi/lo pair
__global__ void __launch_bounds__(256) split_k(
    const float* __restrict__ X, float* __restrict__ Y,
    __half* __restrict__ H, __half* __restrict__ L)
{
    int i = blockIdx.x * 256 + threadIdx.x;
    float4 v = ((const float4*)X)[i];
    ((float4*)Y)[i] = v;
    __half h0,l0,h1,l1,h2,l2,h3,l3;
    hsplit(v.x, h0, l0); hsplit(v.y, h1, l1);
    hsplit(v.z, h2, l2); hsplit(v.w, h3, l3);
    ((__half2*)H)[i*2]   = __halves2half2(h0, h1);
    ((__half2*)H)[i*2+1] = __halves2half2(h2, h3);
    ((__half2*)L)[i*2]   = __halves2half2(l0, l1);
    ((__half2*)L)[i*2+1] = __halves2half2(l2, l3);
}

// ---------------------------------------------------------------------------
// fp16-split tensor-core GEMM (mma.sync.m16n8k16).
// TERMS=3: Ahi·Bhi + Alo·Bhi + Ahi·Blo (fp32-grade; arc/bilinear only).
// TERMS=2: Ahi·Bhi + Ahi·Blo (A fp16-rounded; all in-loop GEMMs).
// ---------------------------------------------------------------------------
#define MG_SMEM (2 * 40960)

template<int NSRC, int TERMS>
__device__ __forceinline__ void mma_core(
    const __half* Ah0, const __half* Al0, const __half* Ah1, const __half* Al1,
    const __half* Ah2, const __half* Al2, const __half* Ah3, const __half* Al3,
    const __half* __restrict__ Whi, const __half* __restrict__ Wlo,
    const float* bias, float* C, __half* Chi, __half* Clo,
    int m0, int n0, int act, int wst)
{
    constexpr int K = NSRC * 256;
    constexpr int NCH = K / 32;
    extern __shared__ char smx[];
    const uint32_t sb = smem_u32(smx);
    const int tid = threadIdx.x;
    const int w   = tid >> 5, lane = tid & 31;
    const int wm  = (w >> 2) << 6;
    const int wn  = (w & 3) << 5;
    const int lrow = tid >> 1, lseg = tid & 1;

    float acc[4][4][4];
    #pragma unroll
    for (int a = 0; a < 4; a++)
        #pragma unroll
        for (int b = 0; b < 4; b++)
            #pragma unroll
            for (int c = 0; c < 4; c++) acc[a][b][c] = 0.f;

    auto prefetch = [&](int ch, int st) {
        const __half* ah = Ah0;
        const __half* al = Al0;
        if (NSRC > 1) {
            int s = ch >> 3;
            if (s == 1) { ah = Ah1; al = Al1; }
            if (NSRC > 2 && s == 2) { ah = Ah2; al = Al2; }
            if (NSRC > 3 && s == 3) { ah = Ah3; al = Al3; }
        }
        int kloc = (ch << 5) & 255;
        const __half* gah = ah + (size_t)(m0 + lrow) * 256 + kloc + lseg * 16;
        const __half* gbh = Whi + (size_t)(n0 + lrow) * K + (ch << 5) + lseg * 16;
        const __half* gbl = Wlo + (size_t)(n0 + lrow) * K + (ch << 5) + lseg * 16;
        uint32_t sa = sb + st * 40960 + lrow * 80 + lseg * 32;
        cp16(sa,              gah); cp16(sa + 16,         gah + 8);
        if (TERMS == 3) {
            const __half* gal = al + (size_t)(m0 + lrow) * 256 + kloc + lseg * 16;
            cp16(sa + 10240,      gal); cp16(sa + 10240 + 16, gal + 8);
        }
        cp16(sa + 20480,      gbh); cp16(sa + 20480 + 16, gbh + 8);
        cp16(sa + 30720,      gbl); cp16(sa + 30720 + 16, gbl + 8);
        asm volatile("cp.async.commit_group;");
    };

    prefetch(0, 0);
    for (int ch = 0; ch < NCH; ch++) {
        asm volatile("cp.async.wait_group 0;");
        __syncthreads();
        if (ch + 1 < NCH) prefetch(ch + 1, (ch + 1) & 1);

        const uint32_t stB = sb + (ch & 1) * 40960;
        #pragma unroll
        for (int kt = 0; kt < 32; kt += 16) {
            uint32_t ahr[4][4], alr[4][4];
            #pragma unroll
            for (int mt = 0; mt < 4; mt++) {
                int row = wm + mt * 16 + (lane & 15);
                int kc  = kt + ((lane >> 4) << 3);
                uint32_t ad = stB + row * 80 + kc * 2;
                ldm_x4(ahr[mt], ad);
                if (TERMS == 3) ldm_x4(alr[mt], ad + 10240);
            }
            #pragma unroll
            for (int ng = 0; ng < 2; ng++) {
                int rn = wn + ng * 16 + ((lane >> 4) << 3) + (lane & 7);
                int kc = kt + (((lane >> 3) & 1) << 3);
                uint32_t bd = stB + 20480 + rn * 80 + kc * 2;
                uint32_t bh[4], bl[4];
                ldm_x4(bh, bd);
                ldm_x4(bl, bd + 10240);
                #pragma unroll
                for (int mt = 0; mt < 4; mt++) {
                    #pragma unroll
                    for (int ns = 0; ns < 2; ns++) {
                        float* c = acc[mt][ng * 2 + ns];
                        mma_f16(c, ahr[mt], bh[2*ns], bh[2*ns+1]);
                        if (TERMS == 3) mma_f16(c, alr[mt], bh[2*ns], bh[2*ns+1]);
                        mma_f16(c, ahr[mt], bl[2*ns], bl[2*ns+1]);
                    }
                }
            }
        }
    }

    #pragma unroll
    for (int mt = 0; mt < 4; mt++) {
        int r0 = m0 + wm + mt * 16 + (lane >> 2);
        #pragma unroll
        for (int ni = 0; ni < 4; ni++) {
            int col = n0 + wn + ni * 8 + ((lane & 3) << 1);
            float b0 = bias ? bias[col]     : 0.f;
            float b1 = bias ? bias[col + 1] : 0.f;
            float v0 = acc[mt][ni][0] + b0, v1 = acc[mt][ni][1] + b1;
            float v2 = acc[mt][ni][2] + b0, v3 = acc[mt][ni][3] + b1;
            if (act == 1) { v0 = gelu_f(v0); v1 = gelu_f(v1); v2 = gelu_f(v2); v3 = gelu_f(v3); }
            else if (act == 2) { v0 = sigmoid_f(v0); v1 = sigmoid_f(v1); v2 = sigmoid_f(v2); v3 = sigmoid_f(v3); }
            if (wst & 1) {
                *(float2*)(C + (size_t)r0 * 256 + col)       = make_float2(v0, v1);
                *(float2*)(C + (size_t)(r0 + 8) * 256 + col) = make_float2(v2, v3);
            }
            if (wst & 2) {
                __half h0,l0,h1,l1,h2,l2,h3,l3;
                hsplit(v0, h0, l0); hsplit(v1, h1, l1);
                hsplit(v2, h2, l2); hsplit(v3, h3, l3);
                *(__half2*)(Chi + (size_t)r0 * 256 + col)       = __halves2half2(h0, h1);
                *(__half2*)(Clo + (size_t)r0 * 256 + col)       = __halves2half2(l0, l1);
                *(__half2*)(Chi + (size_t)(r0 + 8) * 256 + col) = __halves2half2(h2, h3);
                *(__half2*)(Clo + (size_t)(r0 + 8) * 256 + col) = __halves2half2(l2, l3);
            }
        }
    }
}

// ---- GEMM wrappers ----
__global__ void __launch_bounds__(256) mg1_k(
    const __half* ah, const __half* al,
    const __half* whi, const __half* wlo, const float* bias,
    float* C, __half* Chi, __half* Clo, int act, int wst)
{
    mma_core<1,3>(ah,al,0,0,0,0,0,0, whi, wlo, bias, C, Chi, Clo,
                  blockIdx.x << 7, blockIdx.y << 7, act, wst);
}

// both head+sib QKV in one launch (2-term): grid.y = 12
__global__ void __launch_bounds__(256) mg_qkv2_k(
    const __half* ah, const __half* al,
    const __half* hwh, const __half* hwl, const float* hb,
    const __half* swh, const __half* swl, const float* sbb,
    __half* hQh, __half* hQl, __half* hKh, __half* hKl, __half* hVh, __half* hVl,
    __half* sQh, __half* sQl, __half* sKh, __half* sKl, __half* sVh, __half* sVl)
{
    int u = blockIdx.y >> 1;                  // 0..5
    int n0 = (blockIdx.y & 1) << 7;
    bool head = u < 3;
    int s = head ? u : u - 3;
    const __half* wh = (head ? hwh : swh) + s * 65536;
    const __half* wl = (head ? hwl : swl) + s * 65536;
    const float*  bb = (head ? hb  : sbb) + s * 256;
    __half *Ch, *Cl;
    if (head) { Ch = s==0?hQh:(s==1?hKh:hVh); Cl = s==0?hQl:(s==1?hKl:hVl); }
    else      { Ch = s==0?sQh:(s==1?sKh:sVh); Cl = s==0?sQl:(s==1?sKl:sVl); }
    mma_core<1,2>(ah,al,0,0,0,0,0,0, wh, wl, bb, nullptr, Ch, Cl,
                  blockIdx.x << 7, n0, 0, 2);
}

// head out-proj + sib out-proj + child MLP in one launch (2-term): grid.y = 6
__global__ void __launch_bounds__(256) proj3_k(
    const __half* ath, const __half* atl,
    const __half* sah, const __half* sal,
    const __half* hrh, const __half* hrl, const __half* cvh, const __half* cvl,
    const __half* hwoh, const __half* hwol, const float* hob,
    const __half* swoh, const __half* swol, const float* sob,
    const __half* cth, const __half* ctl, const float* ctb,
    __half* hmh, __half* hml, __half* sbh, __half* sbl, __half* cmh, __half* cml)
{
    int u = blockIdx.y >> 1;
    int n0 = (blockIdx.y & 1) << 7;
    if (u == 0)
        mma_core<1,2>(ath,atl,0,0,0,0,0,0, hwoh, hwol, hob, nullptr, hmh, hml,
                      blockIdx.x << 7, n0, 0, 2);
    else if (u == 1)
        mma_core<1,2>(sah,sal,0,0,0,0,0,0, swoh, swol, sob, nullptr, sbh, sbl,
                      blockIdx.x << 7, n0, 0, 2);
    else
        mma_core<2,2>(hrh,hrl,cvh,cvl,0,0,0,0, cth, ctl, ctb, nullptr, cmh, cml,
                      blockIdx.x << 7, n0, 1, 2);
}

// gate(sigmoid)+transform(gelu) fused (2-term): grid.y = 4
__global__ void __launch_bounds__(256) mg_gt_k(
    const __half* a0h, const __half* a0l, const __half* a1h, const __half* a1l,
    const __half* a2h, const __half* a2l, const __half* a3h, const __half* a3l,
    const __half* gwh, const __half* gwl, const __half* twh, const __half* twl,
    const float* gb, const float* tbias, float* G, float* U)
{
    int n0 = (blockIdx.y & 1) << 7;
    if (blockIdx.y < 2)
        mma_core<4,2>(a0h,a0l,a1h,a1l,a2h,a2l,a3h,a3l, gwh, gwl, gb,
                      G, nullptr, nullptr, blockIdx.x << 7, n0, 2, 1);
    else
        mma_core<4,2>(a0h,a0l,a1h,a1l,a2h,a2l,a3h,a3l, twh, twl, tbias,
                      U, nullptr, nullptr, blockIdx.x << 7, n0, 1, 1);
}

// arc head + dep (3-term, feeds scores output): grid.y = 4
__global__ void __launch_bounds__(256) mg_arc_k(
    const __half* hrh, const __half* hrl,
    const __half* awh, const __half* awl, const float* ahb,
    const __half* dwh, const __half* dwl, const float* adb,
    float* Aq, __half* qah, __half* qal, float* Ad)
{
    int u = blockIdx.y >> 1;
    int n0 = (blockIdx.y & 1) << 7;
    if (u == 0)
        mma_core<1,3>(hrh,hrl,0,0,0,0,0,0, awh, awl, ahb, Aq, qah, qal,
                      blockIdx.x << 7, n0, 0, 3);
    else
        mma_core<1,3>(hrh,hrl,0,0,0,0,0,0, dwh, dwl, adb, Ad, nullptr, nullptr,
                      blockIdx.x << 7, n0, 0, 1);
}

// ---------------------------------------------------------------------------
// Tensor-core flash attention: head (z=0, gathered K/V) + sib (z=1, mask).
// 256 threads = 8 warps x 16 query rows. 3-term internally.
// ---------------------------------------------------------------------------
#define ASTR 72
#define PLSZ (128 * ASTR * 2)
#define ATC_SMEM (6 * PLSZ + 1024)

__global__ void __launch_bounds__(256) attnB_k(
    const __half* __restrict__ hQh, const __half* __restrict__ hQl,
    const __half* __restrict__ hKh, const __half* __restrict__ hKl,
    const __half* __restrict__ hVh, const __half* __restrict__ hVl,
    const __half* __restrict__ sQh2, const __half* __restrict__ sQl2,
    const __half* __restrict__ sKh2, const __half* __restrict__ sKl2,
    const __half* __restrict__ sVh2, const __half* __restrict__ sVl2,
    const int* __restrict__ ph, const float* __restrict__ mask,
    __half* __restrict__ hOh, __half* __restrict__ hOl,
    __half* __restrict__ sOh, __half* __restrict__ sOl)
{
    extern __shared__ char smc[];
    __half* sm = (__half*)smc;
    int*    phs = (int*)(smc + 6 * PLSZ);
    float*  msk = (float*)(smc + 6 * PLSZ + 512);

    const int b = blockIdx.x, h = blockIdx.y, mode = blockIdx.z;
    const int t = threadIdx.x;
    const int warp = t >> 5, lane = t & 31;
    const int rowbase = b * NN;
    const uint32_t sb = smem_u32(smc);

    const __half* Qh = mode ? sQh2 : hQh;  const __half* Ql = mode ? sQl2 : hQl;
    const __half* Kh = mode ? sKh2 : hKh;  const __half* Kl = mode ? sKl2 : hKl;
    const __half* Vh = mode ? sVh2 : hVh;  const __half* Vl = mode ? sVl2 : hVl;
    __half* Oh = mode ? sOh : hOh;
    __half* Ol = mode ? sOl : hOl;

    if (t < 128) {
        phs[t] = ph[rowbase + t];
        msk[t] = mask[rowbase + t];
    }
    __syncthreads();

    for (int i = t; i < 1024; i += 256) {
        int row = i >> 3, seg = (i & 7) << 3;
        size_t qoff = (size_t)(rowbase + row) * DM + h * HDD + seg;
        *(uint4*)&sm[row*ASTR + seg]              = *(const uint4*)(Qh + qoff);
        *(uint4*)&sm[128*ASTR + row*ASTR + seg]   = *(const uint4*)(Ql + qoff);
        int src = (mode == 0) ? min(max(phs[row], 0), NN - 1) : row;
        size_t koff = (size_t)(rowbase + src) * DM + h * HDD + seg;
        *(uint4*)&sm[2*128*ASTR + row*ASTR + seg] = *(const uint4*)(Kh + koff);
        *(uint4*)&sm[3*128*ASTR + row*ASTR + seg] = *(const uint4*)(Kl + koff);
        *(uint4*)&sm[4*128*ASTR + row*ASTR + seg] = *(const uint4*)(Vh + koff);
        *(uint4*)&sm[5*128*ASTR + row*ASTR + seg] = *(const uint4*)(Vl + koff);
    }
    __syncthreads();

    const int wm = warp << 4;              // 16 query rows per warp
    float S[16][4];
    #pragma unroll
    for (int g = 0; g < 16; g++)
        #pragma unroll
        for (int c = 0; c < 4; c++) S[g][c] = 0.f;

    // S = Q @ K^T
    #pragma unroll
    for (int kt = 0; kt < 4; kt++) {
        uint32_t ah4[4], al4[4];
        uint32_t ad = sb + ((wm + (lane & 15)) * ASTR + kt*16 + ((lane >> 4) << 3)) * 2;
        ldm_x4(ah4, ad);
        ldm_x4(al4, ad + PLSZ);
        #pragma unroll
        for (int ng = 0; ng < 8; ng++) {
            int rn = ng*16 + ((lane >> 4) << 3) + (lane & 7);
            int kc = kt*16 + (((lane >> 3) & 1) << 3);
            uint32_t bd = sb + 2*PLSZ + (rn * ASTR + kc) * 2;
            uint32_t bh4[4], bl4[4];
            ldm_x4(bh4, bd);
            ldm_x4(bl4, bd + PLSZ);
            #pragma unroll
            for (int ns = 0; ns < 2; ns++) {
                float* c = S[ng*2 + ns];
                mma_f16(c, ah4, bh4[2*ns], bh4[2*ns+1]);
                mma_f16(c, al4, bh4[2*ns], bh4[2*ns+1]);
                mma_f16(c, ah4, bl4[2*ns], bl4[2*ns+1]);
            }
        }
    }

    // scale + mask + row max
    float rmax[2] = {-3.4e38f, -3.4e38f};
    #pragma unroll
    for (int ng = 0; ng < 16; ng++)
        #pragma unroll
        for (int c = 0; c < 4; c++) {
            float v = S[ng][c] * 0.125f;
            if (mode == 1) {
                int row = wm + (lane >> 2) + ((c >> 1) << 3);
                int col = (ng << 3) + ((lane & 3) << 1) + (c & 1);
                bool sib = (phs[col] == phs[row]) && (col != row)
                           && (msk[col] > 0.f) && (msk[row] > 0.f);
                if (!sib) v = -1e9f;
            }
            S[ng][c] = v;
            rmax[c >> 1] = fmaxf(rmax[c >> 1], v);
        }
    #pragma unroll
    for (int i = 0; i < 2; i++) {
        rmax[i] = fmaxf(rmax[i], __shfl_xor_sync(0xffffffffu, rmax[i], 1));
        rmax[i] = fmaxf(rmax[i], __shfl_xor_sync(0xffffffffu, rmax[i], 2));
    }

    // exp + row sum
    float rsum[2] = {0.f, 0.f};
    #pragma unroll
    for (int ng = 0; ng < 16; ng++)
        #pragma unroll
        for (int c = 0; c < 4; c++) {
            float e = __expf(S[ng][c] - rmax[c >> 1]);
            S[ng][c] = e;
            rsum[c >> 1] += e;
        }
    #pragma unroll
    for (int i = 0; i < 2; i++) {
        rsum[i] += __shfl_xor_sync(0xffffffffu, rsum[i], 1);
        rsum[i] += __shfl_xor_sync(0xffffffffu, rsum[i], 2);
    }
    float inv0 = 1.f / rsum[0], inv1 = 1.f / rsum[1];

    // O = P @ V (V via ldmatrix.trans)
    float Oa[8][4];
    #pragma unroll
    for (int g = 0; g < 8; g++)
        #pragma unroll
        for (int c = 0; c < 4; c++) Oa[g][c] = 0.f;

    #pragma unroll
    for (int j = 0; j < 8; j++) {
        uint32_t pph[4], ppl[4];
        psplit2(S[2*j][0],   S[2*j][1],   pph[0], ppl[0]);
        psplit2(S[2*j][2],   S[2*j][3],   pph[1], ppl[1]);
        psplit2(S[2*j+1][0], S[2*j+1][1], pph[2], ppl[2]);
        psplit2(S[2*j+1][2], S[2*j+1][3], pph[3], ppl[3]);
        #pragma unroll
        for (int ng = 0; ng < 4; ng++) {
            int kr = (j << 4) + (lane & 15);
            int nc = (ng << 4) + ((lane >> 4) << 3);
            uint32_t bd = sb + 4*PLSZ + (kr * ASTR + nc) * 2;
            uint32_t bvh[4], bvl[4];
            ldm_x4_t(bvh, bd);
            ldm_x4_t(bvl, bd + PLSZ);
            #pragma unroll
            for (int ns = 0; ns < 2; ns++) {
                float* c = Oa[ng*2 + ns];
                mma_f16(c, pph, bvh[2*ns], bvh[2*ns+1]);
                mma_f16(c, ppl, bvh[2*ns], bvh[2*ns+1]);
                mma_f16(c, pph, bvl[2*ns], bvl[2*ns+1]);
            }
        }
    }

    // epilogue
    #pragma unroll
    for (int ng = 0; ng < 8; ng++) {
        int col = h * HDD + (ng << 3) + ((lane & 3) << 1);
        int r0 = rowbase + wm + (lane >> 2);
        float v0 = Oa[ng][0] * inv0, v1 = Oa[ng][1] * inv0;
        float v2 = Oa[ng][2] * inv1, v3 = Oa[ng][3] * inv1;
        __half h0,l0,h1,l1,h2,l2,h3,l3;
        hsplit(v0, h0, l0); hsplit(v1, h1, l1);
        hsplit(v2, h2, l2); hsplit(v3, h3, l3);
        *(__half2*)(Oh + (size_t)r0 * DM + col)       = __halves2half2(h0, h1);
        *(__half2*)(Ol + (size_t)r0 * DM + col)       = __halves2half2(l0, l1);
        *(__half2*)(Oh + (size_t)(r0 + 8) * DM + col) = __halves2half2(h2, h3);
        *(__half2*)(Ol + (size_t)(r0 + 8) * DM + col) = __halves2half2(l2, l3);
    }
}

// ---------------------------------------------------------------------------
// Child scatter-mean (atomic-free); outputs fp16 pair.
// ---------------------------------------------------------------------------
#define CHILD_SMEM (128 * 128 * 4)

__global__ void __launch_bounds__(128) child_k(
    const float* __restrict__ Hr, const int* __restrict__ ph,
    const float* __restrict__ mask,
    __half* __restrict__ Oh, __half* __restrict__ Ol)
{
    extern __shared__ float sm[];
    __shared__ int   phs[128];
    __shared__ float msk[128], inv[128];
    const int b = blockIdx.x, t = threadIdx.x;
    const int d0 = blockIdx.y << 7;

    phs[t] = min(max(ph[b * 128 + t], 0), 127);
    msk[t] = mask[b * 128 + t];
    for (int i = t; i < 16384; i += 128) sm[i] = 0.f;
    __syncthreads();

    float c = 0.f;
    #pragma unroll 4
    for (int n = 0; n < 128; n++) c += (phs[n] == t) ? msk[n] : 0.f;
    inv[t] = 1.f / fmaxf(c, 1.f);

    #pragma unroll 4
    for (int n = 0; n < 128; n++) {
        int hrow = phs[n];
        sm[(hrow << 7) + t] += Hr[(size_t)(b * 128 + n) * 256 + d0 + t];
    }
    __syncthreads();

    for (int hh = 0; hh < 128; hh++) {
        float v = sm[(hh << 7) + t] * inv[hh];
        __half hb, lb;
        hsplit(v, hb, lb);
        size_t o = (size_t)(b * 128 + hh) * 256 + d0 + t;
        Oh[o] = hb;
        Ol[o] = lb;
    }
}

// ---------------------------------------------------------------------------
// Fused gate*update + residual + LayerNorm: warp per row, 8 rows per block.
// ---------------------------------------------------------------------------
__global__ void __launch_bounds__(256) fuse_ln_k(
    float* __restrict__ Hr, const float* __restrict__ g, const float* __restrict__ u,
    const float* __restrict__ lg, const float* __restrict__ lb,
    __half* __restrict__ Hh, __half* __restrict__ Hl)
{
    int row  = blockIdx.x * 8 + (threadIdx.x >> 5);
    int lane = threadIdx.x & 31;
    size_t base = (size_t)row * 256;
    float x[8];
    float s = 0.f, qq = 0.f;
    #pragma unroll
    for (int i = 0; i < 8; i++) {
        int d = lane + (i << 5);
        float v = Hr[base + d] + g[base + d] * u[base + d];
        x[i] = v; s += v; qq += v * v;
    }
    #pragma unroll
    for (int o = 16; o; o >>= 1) {
        s  += __shfl_xor_sync(0xffffffffu, s, o);
        qq += __shfl_xor_sync(0xffffffffu, qq, o);
    }
    float mu = s * (1.f / 256.f);
    float var = fmaxf(qq * (1.f / 256.f) - mu * mu, 0.f);
    float inv = rsqrtf(var + 1e-5f);
    #pragma unroll
    for (int i = 0; i < 8; i++) {
        int d = lane + (i << 5);
        float y = (x[i] - mu) * inv * lg[d] + lb[d];
        Hr[base + d] = y;
        __half hb, lbv;
        hsplit(y, hb, lbv);
        Hh[base + d] = hb;
        Hl[base + d] = lbv;
    }
}

// ---------------------------------------------------------------------------
// both bias vectors in one launch: grid (MR/8, 2)
// ---------------------------------------------------------------------------
__global__ void __launch_bounds__(256) biasvec2_k(
    const float* __restrict__ X0, const float* __restrict__ w0, const float* __restrict__ c0,
    const float* __restrict__ X1, const float* __restrict__ w1, const float* __restrict__ c1,
    float* __restrict__ o0, float* __restrict__ o1)
{
    int sel = blockIdx.y;
    const float* X = sel ? X1 : X0;
    const float* w = sel ? w1 : w0;
    const float* cb = sel ? c1 : c0;
    float* out = sel ? o1 : o0;
    int row  = blockIdx.x * 8 + (threadIdx.x >> 5);
    int lane = threadIdx.x & 31;
    const float* x = X + (size_t)row * 256;
    float s = 0.f;
    for (int d = lane; d < 256; d += 32) s += x[d] * w[d];
    #pragma unroll
    for (int o = 16; o; o >>= 1) s += __shfl_xor_sync(0xffffffffu, s, o);
    if (lane == 0) out[row] = s + cb[0];
}

// ---------------------------------------------------------------------------
// Final scores (fp32 f32x2 path)
// ---------------------------------------------------------------------------
__device__ __forceinline__ void unpk(unsigned long long p, float& x, float& y) {
    asm("mov.b64 {%0, %1}, %2;" : "=f"(x), "=f"(y) : "l"(p));
}
#define SSM_BYTES ((16*132 * 2) * 4)

__global__ void __launch_bounds__(256, 2) scores2_k(
    const float* __restrict__ T, const float* __restrict__ Hd,
    const float* __restrict__ bh, const float* __restrict__ bd,
    float* __restrict__ S)
{
    extern __shared__ float smx2[];
    float* As = smx2;
    float* Bs = smx2 + 16 * 132;
    const int b = blockIdx.x;
    const int tid = threadIdx.x;
    const int tr = tid >> 4, tc = tid & 15;
    const int ra = tid >> 2, ca = (tid & 3) << 2;
    const float* Ab = T  + (size_t)b * NN * DM;
    const float* Bb = Hd + (size_t)b * NN * DM;

    unsigned long long acc[8][4];
    #pragma unroll
    for (int i = 0; i < 8; i++)
        #pragma unroll
        for (int j = 0; j < 4; j++) acc[i][j] = 0ull;

    float4 a0, a1, b0, b1;
    a0 = *(const float4*)(Ab + (size_t)ra * 256 + ca);
    a1 = *(const float4*)(Ab + (size_t)(ra + 64) * 256 + ca);
    b0 = *(const float4*)(Bb + (size_t)ra * 256 + ca);
    b1 = *(const float4*)(Bb + (size_t)(ra + 64) * 256 + ca);

    for (int kt = 0; kt < 256; kt += 16) {
        __syncthreads();
        As[(ca+0)*132 + ra] = a0.x; As[(ca+1)*132 + ra] = a0.y;
        As[(ca+2)*132 + ra] = a0.z; As[(ca+3)*132 + ra] = a0.w;
        As[(ca+0)*132 + ra + 64] = a1.x; As[(ca+1)*132 + ra + 64] = a1.y;
        As[(ca+2)*132 + ra + 64] = a1.z; As[(ca+3)*132 + ra + 64] = a1.w;
        Bs[(ca+0)*132 + ra] = b0.x; Bs[(ca+1)*132 + ra] = b0.y;
        Bs[(ca+2)*132 + ra] = b0.z; Bs[(ca+3)*132 + ra] = b0.w;
        Bs[(ca+0)*132 + ra + 64] = b1.x; Bs[(ca+1)*132 + ra + 64] = b1.y;
        Bs[(ca+2)*132 + ra + 64] = b1.z; Bs[(ca+3)*132 + ra + 64] = b1.w;
        __syncthreads();
        if (kt + 16 < 256) {
            a0 = *(const float4*)(Ab + (size_t)ra * 256 + kt + 16 + ca);
            a1 = *(const float4*)(Ab + (size_t)(ra + 64) * 256 + kt + 16 + ca);
            b0 = *(const float4*)(Bb + (size_t)ra * 256 + kt + 16 + ca);
            b1 = *(const float4*)(Bb + (size_t)(ra + 64) * 256 + kt + 16 + ca);
        }
        #pragma unroll
        for (int kk = 0; kk < 16; kk++) {
            float4 av0 = *(const float4*)&As[kk*132 + (tr << 2)];
            float4 av1 = *(const float4*)&As[kk*132 + 64 + (tr << 2)];
            ulonglong2 bq0 = *(const ulonglong2*)&Bs[kk*132 + (tc << 2)];
            ulonglong2 bq1 = *(const ulonglong2*)&Bs[kk*132 + 64 + (tc << 2)];
            float a_[8] = {av0.x, av0.y, av0.z, av0.w, av1.x, av1.y, av1.z, av1.w};
            #pragma unroll
            for (int i = 0; i < 8; i++) {
                unsigned long long ap;
                asm("mov.b64 %0, {%1, %1};" : "=l"(ap) : "f"(a_[i]));
                asm("fma.rn.f32x2 %0, %1, %2, %0;" : "+l"(acc[i][0]) : "l"(ap), "l"(bq0.x));
                asm("fma.rn.f32x2 %0, %1, %2, %0;" : "+l"(acc[i][1]) : "l"(ap), "l"(bq0.y));
                asm("fma.rn.f32x2 %0, %1, %2, %0;" : "+l"(acc[i][2]) : "l"(ap), "l"(bq1.x));
                asm("fma.rn.f32x2 %0, %1, %2, %0;" : "+l"(acc[i][3]) : "l"(ap), "l"(bq1.y));
            }
        }
    }

    float cb[8];
    #pragma unroll
    for (int j = 0; j < 8; j++) {
        int c = (j < 4) ? ((tc << 2) + j) : (64 + (tc << 2) + j - 4);
        cb[j] = bh[b * NN + c];
    }
    #pragma unroll
    for (int i = 0; i < 8; i++) {
        int n = (i < 4) ? ((tr << 2) + i) : (64 + (tr << 2) + i - 4);
        float rb = bd[b * NN + n];
        float o[8];
        unpk(acc[i][0], o[0], o[1]); unpk(acc[i][1], o[2], o[3]);
        unpk(acc[i][2], o[4], o[5]); unpk(acc[i][3], o[6], o[7]);
        float4 s0 = {o[0]+rb+cb[0], o[1]+rb+cb[1], o[2]+rb+cb[2], o[3]+rb+cb[3]};
        float4 s1 = {o[4]+rb+cb[4], o[5]+rb+cb[5], o[6]+rb+cb[6], o[7]+rb+cb[7]};
        *(float4*)(S + (size_t)b * NN * NN + (size_t)n * NN + (tc << 2))      = s0;
        *(float4*)(S + (size_t)b * NN * NN + (size_t)n * NN + 64 + (tc << 2)) = s1;
    }
}

// ---------------------------------------------------------------------------
// Host orchestration
// ---------------------------------------------------------------------------
extern "C" void kernel_launch(void* const* d_in, const int* in_sizes, int n_in,
                              void* d_out, int out_size)
{
    const float* Hin    = (const float*)d_in[0];
    const int*   ph     = (const int*)  d_in[1];
    const float* mask   = (const float*)d_in[2];
    const float* ha_w   = (const float*)d_in[3];
    const float* ha_b   = (const float*)d_in[4];
    const float* sa_w   = (const float*)d_in[5];
    const float* sa_b   = (const float*)d_in[6];
    const float* ct_w   = (const float*)d_in[7];
    const float* ct_b   = (const float*)d_in[8];
    const float* gate_w = (const float*)d_in[9];
    const float* gate_b = (const float*)d_in[10];
    const float* tr_w   = (const float*)d_in[11];
    const float* tr_b   = (const float*)d_in[12];
    const float* ln_g   = (const float*)d_in[13];
    const float* ln_b   = (const float*)d_in[14];
    const float* ahw    = (const float*)d_in[15];
    const float* ahb    = (const float*)d_in[16];
    const float* adw    = (const float*)d_in[17];
    const float* adb    = (const float*)d_in[18];
    const float* bil    = (const float*)d_in[19];
    const float* bhw    = (const float*)d_in[20];
    const float* bhb    = (const float*)d_in[21];
    const float* bdw    = (const float*)d_in[22];
    const float* bdb    = (const float*)d_in[23];

    float* Hr     = (float*)d_out;
    float* scores = Hr + (size_t)MR * DM;

    float *qf_, *kf_, *vf_, *ga_, *tu_, *bt_, *aq_, *ad_, *bhv_, *bdv_;
    __half *hrh, *hrl, *ath, *atl, *hmh, *hml, *cmh, *cml, *sbh, *sbl,
           *cvh, *cvl, *qah, *qal, *whi_, *wlo_;
    cudaGetSymbolAddress((void**)&qf_, g_q);
    cudaGetSymbolAddress((void**)&kf_, g_k);
    cudaGetSymbolAddress((void**)&vf_, g_v);
    cudaGetSymbolAddress((void**)&ga_, g_gate);
    cudaGetSymbolAddress((void**)&tu_, g_tr);
    cudaGetSymbolAddress((void**)&bt_, g_bil);
    cudaGetSymbolAddress((void**)&aq_, g_arcq);
    cudaGetSymbolAddress((void**)&ad_, g_arcd);
    cudaGetSymbolAddress((void**)&bhv_, g_bh);
    cudaGetSymbolAddress((void**)&bdv_, g_bd);
    cudaGetSymbolAddress((void**)&hrh, g_hr_h);  cudaGetSymbolAddress((void**)&hrl, g_hr_l);
    cudaGetSymbolAddress((void**)&ath, g_at_h);  cudaGetSymbolAddress((void**)&atl, g_at_l);
    cudaGetSymbolAddress((void**)&hmh, g_hm_h);  cudaGetSymbolAddress((void**)&hml, g_hm_l);
    cudaGetSymbolAddress((void**)&cmh, g_cm_h);  cudaGetSymbolAddress((void**)&cml, g_cm_l);
    cudaGetSymbolAddress((void**)&sbh, g_sb_h);  cudaGetSymbolAddress((void**)&sbl, g_sb_l);
    cudaGetSymbolAddress((void**)&cvh, g_cav_h); cudaGetSymbolAddress((void**)&cvl, g_cav_l);
    cudaGetSymbolAddress((void**)&qah, g_qa_h);  cudaGetSymbolAddress((void**)&qal, g_qa_l);
    cudaGetSymbolAddress((void**)&whi_, g_whi);  cudaGetSymbolAddress((void**)&wlo_, g_wlo);

    // half plane views: hi plane then lo plane inside each fp32 scratch array
    __half* hQh = (__half*)qf_; __half* hQl = hQh + (size_t)MR * DM;
    __half* hKh = (__half*)kf_; __half* hKl = hKh + (size_t)MR * DM;
    __half* hVh = (__half*)vf_; __half* hVl = hVh + (size_t)MR * DM;
    __half* sQh = (__half*)ga_; __half* sQl = sQh + (size_t)MR * DM;
    __half* sKh = (__half*)tu_; __half* sKl = sKh + (size_t)MR * DM;
    __half* sVh = (__half*)bt_; __half* sVl = sVh + (size_t)MR * DM;

    cudaFuncSetAttribute(mg1_k,     cudaFuncAttributeMaxDynamicSharedMemorySize, MG_SMEM);
    cudaFuncSetAttribute(mg_qkv2_k, cudaFuncAttributeMaxDynamicSharedMemorySize, MG_SMEM);
    cudaFuncSetAttribute(proj3_k,   cudaFuncAttributeMaxDynamicSharedMemorySize, MG_SMEM);
    cudaFuncSetAttribute(mg_gt_k,   cudaFuncAttributeMaxDynamicSharedMemorySize, MG_SMEM);
    cudaFuncSetAttribute(mg_arc_k,  cudaFuncAttributeMaxDynamicSharedMemorySize, MG_SMEM);
    cudaFuncSetAttribute(attnB_k,   cudaFuncAttributeMaxDynamicSharedMemorySize, ATC_SMEM);
    cudaFuncSetAttribute(child_k,   cudaFuncAttributeMaxDynamicSharedMemorySize, CHILD_SMEM);

    wconv_k<<<dim3(8, 32, 36), dim3(32, 8)>>>(ha_w, sa_w, ct_w, gate_w, tr_w, ahw, adw, bil);
    split_k<<<MR * DM / 1024, 256>>>(Hin, Hr, hrh, hrl);

    for (int i = 0; i < 3; i++) {
        const __half* hwh = whi_ + WOFF_HA + (size_t)i * 4 * 65536;
        const __half* hwl = wlo_ + WOFF_HA + (size_t)i * 4 * 65536;
        const __half* swh = whi_ + WOFF_SA + (size_t)i * 4 * 65536;
        const __half* swl = wlo_ + WOFF_SA + (size_t)i * 4 * 65536;
        const float*  hb  = ha_b + (size_t)i * 1024;
        const float*  sbb = sa_b + (size_t)i * 1024;

        // both QKV sets in one launch (2-term)
        mg_qkv2_k<<<dim3(256, 12), 256, MG_SMEM>>>(hrh, hrl, hwh, hwl, hb, swh, swl, sbb,
                                                   hQh, hQl, hKh, hKl, hVh, hVl,
                                                   sQh, sQl, sKh, sKl, sVh, sVl);
        // child scatter-mean (independent)
        child_k<<<dim3(256, 2), 128, CHILD_SMEM>>>(Hr, ph, mask, cvh, cvl);
        // both attentions in one launch (3-term internals)
        attnB_k<<<dim3(BB, NHH, 2), 256, ATC_SMEM>>>(hQh, hQl, hKh, hKl, hVh, hVl,
                                                     sQh, sQl, sKh, sKl, sVh, sVl,
                                                     ph, mask, ath, atl, qah, qal);
        // head proj + sib proj + child MLP in one launch (2-term)
        proj3_k<<<dim3(256, 6), 256, MG_SMEM>>>(ath, atl, qah, qal, hrh, hrl, cvh, cvl,
                                                hwh + 3*65536, hwl + 3*65536, hb + 768,
                                                swh + 3*65536, swl + 3*65536, sbb + 768,
                                                whi_ + WOFF_CT + (size_t)i * 131072,
                                                wlo_ + WOFF_CT + (size_t)i * 131072,
                                                ct_b + (size_t)i * 256,
                                                hmh, hml, sbh, sbl, cmh, cml);
        // gated fuse (2-term)
        mg_gt_k<<<dim3(256, 4), 256, MG_SMEM>>>(hrh, hrl, hmh, hml, cmh, cml, sbh, sbl,
                                                whi_ + WOFF_GATE + (size_t)i * 262144,
                                                wlo_ + WOFF_GATE + (size_t)i * 262144,
                                                whi_ + WOFF_TR + (size_t)i * 262144,
                                                wlo_ + WOFF_TR + (size_t)i * 262144,
                                                gate_b + (size_t)i * 256,
                                                tr_b   + (size_t)i * 256, ga_, tu_);
        fuse_ln_k<<<MR / 8, 256>>>(Hr, ga_, tu_, ln_g + (size_t)i * 256,
                                   ln_b + (size_t)i * 256, hrh, hrl);
    }

    // final biaffine scorer (3-term: feeds scores output directly)
    mg_arc_k<<<dim3(256, 4), 256, MG_SMEM>>>(hrh, hrl,
                                             whi_ + WOFF_ARCH, wlo_ + WOFF_ARCH, ahb,
                                             whi_ + WOFF_ARCD, wlo_ + WOFF_ARCD, adb,
                                             aq_, qah, qal, ad_);
    mg1_k<<<dim3(256, 2), 256, MG_SMEM>>>(qah, qal, whi_ + WOFF_BIL, wlo_ + WOFF_BIL,
                                          nullptr, bt_, nullptr, nullptr, 0, 1);
    biasvec2_k<<<dim3(MR / 8, 2), 256>>>(aq_, bhw, bhb, ad_, bdw, bdb, bhv_, bdv_);
    scores2_k<<<BB, 256, SSM_BYTES>>>(bt_, ad_, bhv_, bdv_, scores);
}

// round 17
// speedup vs baseline: 1.7252x; 1.1715x over previous
#include <cuda_runtime.h>
#include <cuda_fp16.h>
#include <math.h>
#include <stdint.h>

#define BB   256
#define NN   128
#define DM   256
#define NHH  4
#define HDD  64
#define MR   (BB*NN)

// weight plane offsets (elements) in transposed fp16 weight planes [n][k]
#define WOFF_HA   0u
#define WOFF_SA   786432u
#define WOFF_CT   1572864u
#define WOFF_GATE 1966080u
#define WOFF_TR   2752512u
#define WOFF_ARCH 3538944u
#define WOFF_ARCD 3604480u
#define WOFF_BIL  3670016u
#define WTOT      3735552u

// ---------------- scratch ----------------
__device__ float g_q[MR*DM];      // head Q hi|lo half planes
__device__ float g_k[MR*DM];      // head K hi|lo
__device__ float g_v[MR*DM];      // head V hi|lo
__device__ float g_gate[MR*DM];   // sib Q hi|lo, later G fp32
__device__ float g_tr[MR*DM];     // sib K hi|lo, later U fp32
__device__ float g_bil[MR*DM];    // sib V hi|lo, later T fp32
__device__ float g_arcq[MR*DM];   // fp32 h_head
__device__ float g_arcd[MR*DM];   // fp32 h_dep
__device__ float g_bh[MR];
__device__ float g_bd[MR];
__device__ __half g_hr_h[MR*DM],  g_hr_l[MR*DM];
__device__ __half g_at_h[MR*DM],  g_at_l[MR*DM];   // head attn out
__device__ __half g_hm_h[MR*DM],  g_hm_l[MR*DM];
__device__ __half g_cm_h[MR*DM],  g_cm_l[MR*DM];
__device__ __half g_sb_h[MR*DM],  g_sb_l[MR*DM];
__device__ __half g_cav_h[MR*DM], g_cav_l[MR*DM];
__device__ __half g_qa_h[MR*DM],  g_qa_l[MR*DM];   // sib attn out / arc planes
__device__ __half g_whi[WTOT],    g_wlo[WTOT];

// ---------------- helpers ----------------
__device__ __forceinline__ float gelu_f(float x) {
    return 0.5f * x * (1.0f + erff(x * 0.7071067811865475f));
}
__device__ __forceinline__ float sigmoid_f(float x) {
    return 1.0f / (1.0f + expf(-x));
}
__device__ __forceinline__ void hsplit(float x, __half& h, __half& l) {
    h = __float2half_rn(x);
    l = __float2half_rn(x - __half2float(h));
}
__device__ __forceinline__ void psplit2(float a, float b, uint32_t& hi, uint32_t& lo) {
    __half ha = __float2half_rn(a), hb = __float2half_rn(b);
    __half la = __float2half_rn(a - __half2float(ha));
    __half lb = __float2half_rn(b - __half2float(hb));
    __half2 H = __halves2half2(ha, hb), L = __halves2half2(la, lb);
    hi = *(uint32_t*)&H;
    lo = *(uint32_t*)&L;
}
__device__ __forceinline__ uint32_t smem_u32(const void* p) {
    uint32_t a;
    asm("{ .reg .u64 t; cvta.to.shared.u64 t, %1; cvt.u32.u64 %0, t; }" : "=r"(a) : "l"(p));
    return a;
}
__device__ __forceinline__ void cp16(uint32_t saddr, const void* gaddr) {
    asm volatile("cp.async.cg.shared.global [%0], [%1], 16;" :: "r"(saddr), "l"(gaddr));
}
__device__ __forceinline__ void ldm_x4(uint32_t* r, uint32_t saddr) {
    asm volatile("ldmatrix.sync.aligned.m8n8.x4.shared.b16 {%0,%1,%2,%3}, [%4];"
        : "=r"(r[0]), "=r"(r[1]), "=r"(r[2]), "=r"(r[3]) : "r"(saddr));
}
__device__ __forceinline__ void ldm_x4_t(uint32_t* r, uint32_t saddr) {
    asm volatile("ldmatrix.sync.aligned.m8n8.x4.trans.shared.b16 {%0,%1,%2,%3}, [%4];"
        : "=r"(r[0]), "=r"(r[1]), "=r"(r[2]), "=r"(r[3]) : "r"(saddr));
}
__device__ __forceinline__ void mma_f16(float* c, const uint32_t* a, uint32_t b0, uint32_t b1) {
    asm volatile("mma.sync.aligned.m16n8k16.row.col.f32.f16.f16.f32 "
        "{%0,%1,%2,%3}, {%4,%5,%6,%7}, {%8,%9}, {%0,%1,%2,%3};"
        : "+f"(c[0]), "+f"(c[1]), "+f"(c[2]), "+f"(c[3])
        : "r"(a[0]), "r"(a[1]), "r"(a[2]), "r"(a[3]), "r"(b0), "r"(b1));
}

// ---------------------------------------------------------------------------
// Weight transpose + fp16 hi/lo split: W[k][n] -> plane[n*K + k]
// ---------------------------------------------------------------------------
__global__ void __launch_bounds__(256) wconv_k(
    const float* __restrict__ ha, const float* __restrict__ sa,
    const float* __restrict__ ct, const float* __restrict__ gw,
    const float* __restrict__ tw, const float* __restrict__ ahw,
    const float* __restrict__ adw, const float* __restrict__ bil)
{
    int slot = blockIdx.z;
    const float* src; int K; size_t dst;
    if (slot < 12)      { src = ha + (size_t)slot * 65536;       K = 256;  dst = WOFF_HA   + (size_t)slot * 65536; }
    else if (slot < 24) { src = sa + (size_t)(slot-12) * 65536;  K = 256;  dst = WOFF_SA   + (size_t)(slot-12) * 65536; }
    else if (slot < 27) { src = ct + (size_t)(slot-24) * 131072; K = 512;  dst = WOFF_CT   + (size_t)(slot-24) * 131072; }
    else if (slot < 30) { src = gw + (size_t)(slot-27) * 262144; K = 1024; dst = WOFF_GATE + (size_t)(slot-27) * 262144; }
    else if (slot < 33) { src = tw + (size_t)(slot-30) * 262144; K = 1024; dst = WOFF_TR   + (size_t)(slot-30) * 262144; }
    else if (slot == 33){ src = ahw; K = 256; dst = WOFF_ARCH; }
    else if (slot == 34){ src = adw; K = 256; dst = WOFF_ARCD; }
    else                { src = bil; K = 256; dst = WOFF_BIL; }

    int k0 = blockIdx.y * 32;
    if (k0 >= K) return;
    int n0 = blockIdx.x * 32;
    int tx = threadIdx.x, ty = threadIdx.y;

    __shared__ float tile[32][33];
    #pragma unroll
    for (int i = 0; i < 4; i++)
        tile[ty + 8*i][tx] = src[(size_t)(k0 + ty + 8*i) * 256 + n0 + tx];
    __syncthreads();
    #pragma unroll
    for (int i = 0; i < 4; i++) {
        float v = tile[tx][ty + 8*i];
        __half h, l;
        hsplit(v, h, l);
        size_t o = dst + (size_t)(n0 + ty + 8*i) * K + k0 + tx;
        g_whi[o] = h;
        g_wlo[o] = l;
    }
}

// Hin -> Hr fp32 copy + fp16 hi/lo pair
__global__ void __launch_bounds__(256) split_k(
    const float* __restrict__ X, float* __restrict__ Y,
    __half* __restrict__ H, __half* __restrict__ L)
{
    int i = blockIdx.x * 256 + threadIdx.x;
    float4 v = ((const float4*)X)[i];
    ((float4*)Y)[i] = v;
    __half h0,l0,h1,l1,h2,l2,h3,l3;
    hsplit(v.x, h0, l0); hsplit(v.y, h1, l1);
    hsplit(v.z, h2, l2); hsplit(v.w, h3, l3);
    ((__half2*)H)[i*2]   = __halves2half2(h0, h1);
    ((__half2*)H)[i*2+1] = __halves2half2(h2, h3);
    ((__half2*)L)[i*2]   = __halves2half2(l0, l1);
    ((__half2*)L)[i*2+1] = __halves2half2(l2, l3);
}

// ---------------------------------------------------------------------------
// fp16-split tensor-core GEMM (mma.sync.m16n8k16).
// TERMS=3: Ahi·Bhi + Alo·Bhi + Ahi·Blo (fp32-grade; arc/bilinear only).
// TERMS=2: Ahi·Bhi + Ahi·Blo (A fp16-rounded).
// TERMS=1: Ahi·Bhi (pure fp16; all in-loop GEMMs — error damped by
//          activation/gating/LN, validated empirically R14/R15).
// ---------------------------------------------------------------------------
#define MG_SMEM (2 * 40960)

template<int NSRC, int TERMS>
__device__ __forceinline__ void mma_core(
    const __half* Ah0, const __half* Al0, const __half* Ah1, const __half* Al1,
    const __half* Ah2, const __half* Al2, const __half* Ah3, const __half* Al3,
    const __half* __restrict__ Whi, const __half* __restrict__ Wlo,
    const float* bias, float* C, __half* Chi, __half* Clo,
    int m0, int n0, int act, int wst)
{
    constexpr int K = NSRC * 256;
    constexpr int NCH = K / 32;
    extern __shared__ char smx[];
    const uint32_t sb = smem_u32(smx);
    const int tid = threadIdx.x;
    const int w   = tid >> 5, lane = tid & 31;
    const int wm  = (w >> 2) << 6;
    const int wn  = (w & 3) << 5;
    const int lrow = tid >> 1, lseg = tid & 1;

    float acc[4][4][4];
    #pragma unroll
    for (int a = 0; a < 4; a++)
        #pragma unroll
        for (int b = 0; b < 4; b++)
            #pragma unroll
            for (int c = 0; c < 4; c++) acc[a][b][c] = 0.f;

    auto prefetch = [&](int ch, int st) {
        const __half* ah = Ah0;
        const __half* al = Al0;
        if (NSRC > 1) {
            int s = ch >> 3;
            if (s == 1) { ah = Ah1; al = Al1; }
            if (NSRC > 2 && s == 2) { ah = Ah2; al = Al2; }
            if (NSRC > 3 && s == 3) { ah = Ah3; al = Al3; }
        }
        int kloc = (ch << 5) & 255;
        const __half* gah = ah + (size_t)(m0 + lrow) * 256 + kloc + lseg * 16;
        const __half* gbh = Whi + (size_t)(n0 + lrow) * K + (ch << 5) + lseg * 16;
        uint32_t sa = sb + st * 40960 + lrow * 80 + lseg * 32;
        cp16(sa,              gah); cp16(sa + 16,         gah + 8);
        if (TERMS == 3) {
            const __half* gal = al + (size_t)(m0 + lrow) * 256 + kloc + lseg * 16;
            cp16(sa + 10240,      gal); cp16(sa + 10240 + 16, gal + 8);
        }
        cp16(sa + 20480,      gbh); cp16(sa + 20480 + 16, gbh + 8);
        if (TERMS >= 2) {
            const __half* gbl = Wlo + (size_t)(n0 + lrow) * K + (ch << 5) + lseg * 16;
            cp16(sa + 30720,      gbl); cp16(sa + 30720 + 16, gbl + 8);
        }
        asm volatile("cp.async.commit_group;");
    };

    prefetch(0, 0);
    for (int ch = 0; ch < NCH; ch++) {
        asm volatile("cp.async.wait_group 0;");
        __syncthreads();
        if (ch + 1 < NCH) prefetch(ch + 1, (ch + 1) & 1);

        const uint32_t stB = sb + (ch & 1) * 40960;
        #pragma unroll
        for (int kt = 0; kt < 32; kt += 16) {
            uint32_t ahr[4][4], alr[4][4];
            #pragma unroll
            for (int mt = 0; mt < 4; mt++) {
                int row = wm + mt * 16 + (lane & 15);
                int kc  = kt + ((lane >> 4) << 3);
                uint32_t ad = stB + row * 80 + kc * 2;
                ldm_x4(ahr[mt], ad);
                if (TERMS == 3) ldm_x4(alr[mt], ad + 10240);
            }
            #pragma unroll
            for (int ng = 0; ng < 2; ng++) {
                int rn = wn + ng * 16 + ((lane >> 4) << 3) + (lane & 7);
                int kc = kt + (((lane >> 3) & 1) << 3);
                uint32_t bd = stB + 20480 + rn * 80 + kc * 2;
                uint32_t bh[4], bl[4];
                ldm_x4(bh, bd);
                if (TERMS >= 2) ldm_x4(bl, bd + 10240);
                #pragma unroll
                for (int mt = 0; mt < 4; mt++) {
                    #pragma unroll
                    for (int ns = 0; ns < 2; ns++) {
                        float* c = acc[mt][ng * 2 + ns];
                        mma_f16(c, ahr[mt], bh[2*ns], bh[2*ns+1]);
                        if (TERMS == 3) mma_f16(c, alr[mt], bh[2*ns], bh[2*ns+1]);
                        if (TERMS >= 2) mma_f16(c, ahr[mt], bl[2*ns], bl[2*ns+1]);
                    }
                }
            }
        }
    }

    #pragma unroll
    for (int mt = 0; mt < 4; mt++) {
        int r0 = m0 + wm + mt * 16 + (lane >> 2);
        #pragma unroll
        for (int ni = 0; ni < 4; ni++) {
            int col = n0 + wn + ni * 8 + ((lane & 3) << 1);
            float b0 = bias ? bias[col]     : 0.f;
            float b1 = bias ? bias[col + 1] : 0.f;
            float v0 = acc[mt][ni][0] + b0, v1 = acc[mt][ni][1] + b1;
            float v2 = acc[mt][ni][2] + b0, v3 = acc[mt][ni][3] + b1;
            if (act == 1) { v0 = gelu_f(v0); v1 = gelu_f(v1); v2 = gelu_f(v2); v3 = gelu_f(v3); }
            else if (act == 2) { v0 = sigmoid_f(v0); v1 = sigmoid_f(v1); v2 = sigmoid_f(v2); v3 = sigmoid_f(v3); }
            if (wst & 1) {
                *(float2*)(C + (size_t)r0 * 256 + col)       = make_float2(v0, v1);
                *(float2*)(C + (size_t)(r0 + 8) * 256 + col) = make_float2(v2, v3);
            }
            if (wst & 2) {
                __half h0,l0,h1,l1,h2,l2,h3,l3;
                hsplit(v0, h0, l0); hsplit(v1, h1, l1);
                hsplit(v2, h2, l2); hsplit(v3, h3, l3);
                *(__half2*)(Chi + (size_t)r0 * 256 + col)       = __halves2half2(h0, h1);
                *(__half2*)(Clo + (size_t)r0 * 256 + col)       = __halves2half2(l0, l1);
                *(__half2*)(Chi + (size_t)(r0 + 8) * 256 + col) = __halves2half2(h2, h3);
                *(__half2*)(Clo + (size_t)(r0 + 8) * 256 + col) = __halves2half2(l2, l3);
            }
        }
    }
}

// ---- GEMM wrappers ----
__global__ void __launch_bounds__(256) mg1_k(
    const __half* ah, const __half* al,
    const __half* whi, const __half* wlo, const float* bias,
    float* C, __half* Chi, __half* Clo, int act, int wst)
{
    mma_core<1,3>(ah,al,0,0,0,0,0,0, whi, wlo, bias, C, Chi, Clo,
                  blockIdx.x << 7, blockIdx.y << 7, act, wst);
}

// both head+sib QKV in one launch (1-term): grid.y = 12
__global__ void __launch_bounds__(256) mg_qkv2_k(
    const __half* ah, const __half* al,
    const __half* hwh, const __half* hwl, const float* hb,
    const __half* swh, const __half* swl, const float* sbb,
    __half* hQh, __half* hQl, __half* hKh, __half* hKl, __half* hVh, __half* hVl,
    __half* sQh, __half* sQl, __half* sKh, __half* sKl, __half* sVh, __half* sVl)
{
    int u = blockIdx.y >> 1;                  // 0..5
    int n0 = (blockIdx.y & 1) << 7;
    bool head = u < 3;
    int s = head ? u : u - 3;
    const __half* wh = (head ? hwh : swh) + s * 65536;
    const __half* wl = (head ? hwl : swl) + s * 65536;
    const float*  bb = (head ? hb  : sbb) + s * 256;
    __half *Ch, *Cl;
    if (head) { Ch = s==0?hQh:(s==1?hKh:hVh); Cl = s==0?hQl:(s==1?hKl:hVl); }
    else      { Ch = s==0?sQh:(s==1?sKh:sVh); Cl = s==0?sQl:(s==1?sKl:sVl); }
    mma_core<1,1>(ah,al,0,0,0,0,0,0, wh, wl, bb, nullptr, Ch, Cl,
                  blockIdx.x << 7, n0, 0, 2);
}

// head out-proj + sib out-proj + child MLP in one launch (1-term): grid.y = 6
__global__ void __launch_bounds__(256) proj3_k(
    const __half* ath, const __half* atl,
    const __half* sah, const __half* sal,
    const __half* hrh, const __half* hrl, const __half* cvh, const __half* cvl,
    const __half* hwoh, const __half* hwol, const float* hob,
    const __half* swoh, const __half* swol, const float* sob,
    const __half* cth, const __half* ctl, const float* ctb,
    __half* hmh, __half* hml, __half* sbh, __half* sbl, __half* cmh, __half* cml)
{
    int u = blockIdx.y >> 1;
    int n0 = (blockIdx.y & 1) << 7;
    if (u == 0)
        mma_core<1,1>(ath,atl,0,0,0,0,0,0, hwoh, hwol, hob, nullptr, hmh, hml,
                      blockIdx.x << 7, n0, 0, 2);
    else if (u == 1)
        mma_core<1,1>(sah,sal,0,0,0,0,0,0, swoh, swol, sob, nullptr, sbh, sbl,
                      blockIdx.x << 7, n0, 0, 2);
    else
        mma_core<2,1>(hrh,hrl,cvh,cvl,0,0,0,0, cth, ctl, ctb, nullptr, cmh, cml,
                      blockIdx.x << 7, n0, 1, 2);
}

// gate(sigmoid)+transform(gelu) fused (1-term): grid.y = 4
__global__ void __launch_bounds__(256) mg_gt_k(
    const __half* a0h, const __half* a0l, const __half* a1h, const __half* a1l,
    const __half* a2h, const __half* a2l, const __half* a3h, const __half* a3l,
    const __half* gwh, const __half* gwl, const __half* twh, const __half* twl,
    const float* gb, const float* tbias, float* G, float* U)
{
    int n0 = (blockIdx.y & 1) << 7;
    if (blockIdx.y < 2)
        mma_core<4,1>(a0h,a0l,a1h,a1l,a2h,a2l,a3h,a3l, gwh, gwl, gb,
                      G, nullptr, nullptr, blockIdx.x << 7, n0, 2, 1);
    else
        mma_core<4,1>(a0h,a0l,a1h,a1l,a2h,a2l,a3h,a3l, twh, twl, tbias,
                      U, nullptr, nullptr, blockIdx.x << 7, n0, 1, 1);
}

// arc head + dep (3-term, feeds scores output): grid.y = 4
__global__ void __launch_bounds__(256) mg_arc_k(
    const __half* hrh, const __half* hrl,
    const __half* awh, const __half* awl, const float* ahb,
    const __half* dwh, const __half* dwl, const float* adb,
    float* Aq, __half* qah, __half* qal, float* Ad)
{
    int u = blockIdx.y >> 1;
    int n0 = (blockIdx.y & 1) << 7;
    if (u == 0)
        mma_core<1,3>(hrh,hrl,0,0,0,0,0,0, awh, awl, ahb, Aq, qah, qal,
                      blockIdx.x << 7, n0, 0, 3);
    else
        mma_core<1,3>(hrh,hrl,0,0,0,0,0,0, dwh, dwl, adb, Ad, nullptr, nullptr,
                      blockIdx.x << 7, n0, 0, 1);
}

// ---------------------------------------------------------------------------
// Tensor-core flash attention: head (z=0, gathered K/V) + sib (z=1, mask).
// 256 threads = 8 warps x 16 query rows. 3-term internally.
// ---------------------------------------------------------------------------
#define ASTR 72
#define PLSZ (128 * ASTR * 2)
#define ATC_SMEM (6 * PLSZ + 1024)

__global__ void __launch_bounds__(256) attnB_k(
    const __half* __restrict__ hQh, const __half* __restrict__ hQl,
    const __half* __restrict__ hKh, const __half* __restrict__ hKl,
    const __half* __restrict__ hVh, const __half* __restrict__ hVl,
    const __half* __restrict__ sQh2, const __half* __restrict__ sQl2,
    const __half* __restrict__ sKh2, const __half* __restrict__ sKl2,
    const __half* __restrict__ sVh2, const __half* __restrict__ sVl2,
    const int* __restrict__ ph, const float* __restrict__ mask,
    __half* __restrict__ hOh, __half* __restrict__ hOl,
    __half* __restrict__ sOh, __half* __restrict__ sOl)
{
    extern __shared__ char smc[];
    __half* sm = (__half*)smc;
    int*    phs = (int*)(smc + 6 * PLSZ);
    float*  msk = (float*)(smc + 6 * PLSZ + 512);

    const int b = blockIdx.x, h = blockIdx.y, mode = blockIdx.z;
    const int t = threadIdx.x;
    const int warp = t >> 5, lane = t & 31;
    const int rowbase = b * NN;
    const uint32_t sb = smem_u32(smc);

    const __half* Qh = mode ? sQh2 : hQh;  const __half* Ql = mode ? sQl2 : hQl;
    const __half* Kh = mode ? sKh2 : hKh;  const __half* Kl = mode ? sKl2 : hKl;
    const __half* Vh = mode ? sVh2 : hVh;  const __half* Vl = mode ? sVl2 : hVl;
    __half* Oh = mode ? sOh : hOh;
    __half* Ol = mode ? sOl : hOl;

    if (t < 128) {
        phs[t] = ph[rowbase + t];
        msk[t] = mask[rowbase + t];
    }
    __syncthreads();

    for (int i = t; i < 1024; i += 256) {
        int row = i >> 3, seg = (i & 7) << 3;
        size_t qoff = (size_t)(rowbase + row) * DM + h * HDD + seg;
        *(uint4*)&sm[row*ASTR + seg]              = *(const uint4*)(Qh + qoff);
        *(uint4*)&sm[128*ASTR + row*ASTR + seg]   = *(const uint4*)(Ql + qoff);
        int src = (mode == 0) ? min(max(phs[row], 0), NN - 1) : row;
        size_t koff = (size_t)(rowbase + src) * DM + h * HDD + seg;
        *(uint4*)&sm[2*128*ASTR + row*ASTR + seg] = *(const uint4*)(Kh + koff);
        *(uint4*)&sm[3*128*ASTR + row*ASTR + seg] = *(const uint4*)(Kl + koff);
        *(uint4*)&sm[4*128*ASTR + row*ASTR + seg] = *(const uint4*)(Vh + koff);
        *(uint4*)&sm[5*128*ASTR + row*ASTR + seg] = *(const uint4*)(Vl + koff);
    }
    __syncthreads();

    const int wm = warp << 4;              // 16 query rows per warp
    float S[16][4];
    #pragma unroll
    for (int g = 0; g < 16; g++)
        #pragma unroll
        for (int c = 0; c < 4; c++) S[g][c] = 0.f;

    // S = Q @ K^T
    #pragma unroll
    for (int kt = 0; kt < 4; kt++) {
        uint32_t ah4[4], al4[4];
        uint32_t ad = sb + ((wm + (lane & 15)) * ASTR + kt*16 + ((lane >> 4) << 3)) * 2;
        ldm_x4(ah4, ad);
        ldm_x4(al4, ad + PLSZ);
        #pragma unroll
        for (int ng = 0; ng < 8; ng++) {
            int rn = ng*16 + ((lane >> 4) << 3) + (lane & 7);
            int kc = kt*16 + (((lane >> 3) & 1) << 3);
            uint32_t bd = sb + 2*PLSZ + (rn * ASTR + kc) * 2;
            uint32_t bh4[4], bl4[4];
            ldm_x4(bh4, bd);
            ldm_x4(bl4, bd + PLSZ);
            #pragma unroll
            for (int ns = 0; ns < 2; ns++) {
                float* c = S[ng*2 + ns];
                mma_f16(c, ah4, bh4[2*ns], bh4[2*ns+1]);
                mma_f16(c, al4, bh4[2*ns], bh4[2*ns+1]);
                mma_f16(c, ah4, bl4[2*ns], bl4[2*ns+1]);
            }
        }
    }

    // scale + mask + row max
    float rmax[2] = {-3.4e38f, -3.4e38f};
    #pragma unroll
    for (int ng = 0; ng < 16; ng++)
        #pragma unroll
        for (int c = 0; c < 4; c++) {
            float v = S[ng][c] * 0.125f;
            if (mode == 1) {
                int row = wm + (lane >> 2) + ((c >> 1) << 3);
                int col = (ng << 3) + ((lane & 3) << 1) + (c & 1);
                bool sib = (phs[col] == phs[row]) && (col != row)
                           && (msk[col] > 0.f) && (msk[row] > 0.f);
                if (!sib) v = -1e9f;
            }
            S[ng][c] = v;
            rmax[c >> 1] = fmaxf(rmax[c >> 1], v);
        }
    #pragma unroll
    for (int i = 0; i < 2; i++) {
        rmax[i] = fmaxf(rmax[i], __shfl_xor_sync(0xffffffffu, rmax[i], 1));
        rmax[i] = fmaxf(rmax[i], __shfl_xor_sync(0xffffffffu, rmax[i], 2));
    }

    // exp + row sum
    float rsum[2] = {0.f, 0.f};
    #pragma unroll
    for (int ng = 0; ng < 16; ng++)
        #pragma unroll
        for (int c = 0; c < 4; c++) {
            float e = __expf(S[ng][c] - rmax[c >> 1]);
            S[ng][c] = e;
            rsum[c >> 1] += e;
        }
    #pragma unroll
    for (int i = 0; i < 2; i++) {
        rsum[i] += __shfl_xor_sync(0xffffffffu, rsum[i], 1);
        rsum[i] += __shfl_xor_sync(0xffffffffu, rsum[i], 2);
    }
    float inv0 = 1.f / rsum[0], inv1 = 1.f / rsum[1];

    // O = P @ V (V via ldmatrix.trans)
    float Oa[8][4];
    #pragma unroll
    for (int g = 0; g < 8; g++)
        #pragma unroll
        for (int c = 0; c < 4; c++) Oa[g][c] = 0.f;

    #pragma unroll
    for (int j = 0; j < 8; j++) {
        uint32_t pph[4], ppl[4];
        psplit2(S[2*j][0],   S[2*j][1],   pph[0], ppl[0]);
        psplit2(S[2*j][2],   S[2*j][3],   pph[1], ppl[1]);
        psplit2(S[2*j+1][0], S[2*j+1][1], pph[2], ppl[2]);
        psplit2(S[2*j+1][2], S[2*j+1][3], pph[3], ppl[3]);
        #pragma unroll
        for (int ng = 0; ng < 4; ng++) {
            int kr = (j << 4) + (lane & 15);
            int nc = (ng << 4) + ((lane >> 4) << 3);
            uint32_t bd = sb + 4*PLSZ + (kr * ASTR + nc) * 2;
            uint32_t bvh[4], bvl[4];
            ldm_x4_t(bvh, bd);
            ldm_x4_t(bvl, bd + PLSZ);
            #pragma unroll
            for (int ns = 0; ns < 2; ns++) {
                float* c = Oa[ng*2 + ns];
                mma_f16(c, pph, bvh[2*ns], bvh[2*ns+1]);
                mma_f16(c, ppl, bvh[2*ns], bvh[2*ns+1]);
                mma_f16(c, pph, bvl[2*ns], bvl[2*ns+1]);
            }
        }
    }

    // epilogue
    #pragma unroll
    for (int ng = 0; ng < 8; ng++) {
        int col = h * HDD + (ng << 3) + ((lane & 3) << 1);
        int r0 = rowbase + wm + (lane >> 2);
        float v0 = Oa[ng][0] * inv0, v1 = Oa[ng][1] * inv0;
        float v2 = Oa[ng][2] * inv1, v3 = Oa[ng][3] * inv1;
        __half h0,l0,h1,l1,h2,l2,h3,l3;
        hsplit(v0, h0, l0); hsplit(v1, h1, l1);
        hsplit(v2, h2, l2); hsplit(v3, h3, l3);
        *(__half2*)(Oh + (size_t)r0 * DM + col)       = __halves2half2(h0, h1);
        *(__half2*)(Ol + (size_t)r0 * DM + col)       = __halves2half2(l0, l1);
        *(__half2*)(Oh + (size_t)(r0 + 8) * DM + col) = __halves2half2(h2, h3);
        *(__half2*)(Ol + (size_t)(r0 + 8) * DM + col) = __halves2half2(l2, l3);
    }
}

// ---------------------------------------------------------------------------
// Child scatter-mean (atomic-free); outputs fp16 pair.
// ---------------------------------------------------------------------------
#define CHILD_SMEM (128 * 128 * 4)

__global__ void __launch_bounds__(128) child_k(
    const float* __restrict__ Hr, const int* __restrict__ ph,
    const float* __restrict__ mask,
    __half* __restrict__ Oh, __half* __restrict__ Ol)
{
    extern __shared__ float sm[];
    __shared__ int   phs[128];
    __shared__ float msk[128], inv[128];
    const int b = blockIdx.x, t = threadIdx.x;
    const int d0 = blockIdx.y << 7;

    phs[t] = min(max(ph[b * 128 + t], 0), 127);
    msk[t] = mask[b * 128 + t];
    for (int i = t; i < 16384; i += 128) sm[i] = 0.f;
    __syncthreads();

    float c = 0.f;
    #pragma unroll 4
    for (int n = 0; n < 128; n++) c += (phs[n] == t) ? msk[n] : 0.f;
    inv[t] = 1.f / fmaxf(c, 1.f);

    #pragma unroll 4
    for (int n = 0; n < 128; n++) {
        int hrow = phs[n];
        sm[(hrow << 7) + t] += Hr[(size_t)(b * 128 + n) * 256 + d0 + t];
    }
    __syncthreads();

    for (int hh = 0; hh < 128; hh++) {
        float v = sm[(hh << 7) + t] * inv[hh];
        __half hb, lb;
        hsplit(v, hb, lb);
        size_t o = (size_t)(b * 128 + hh) * 256 + d0 + t;
        Oh[o] = hb;
        Ol[o] = lb;
    }
}

// ---------------------------------------------------------------------------
// Fused gate*update + residual + LayerNorm: warp per row, 8 rows per block.
// ---------------------------------------------------------------------------
__global__ void __launch_bounds__(256) fuse_ln_k(
    float* __restrict__ Hr, const float* __restrict__ g, const float* __restrict__ u,
    const float* __restrict__ lg, const float* __restrict__ lb,
    __half* __restrict__ Hh, __half* __restrict__ Hl)
{
    int row  = blockIdx.x * 8 + (threadIdx.x >> 5);
    int lane = threadIdx.x & 31;
    size_t base = (size_t)row * 256;
    float x[8];
    float s = 0.f, qq = 0.f;
    #pragma unroll
    for (int i = 0; i < 8; i++) {
        int d = lane + (i << 5);
        float v = Hr[base + d] + g[base + d] * u[base + d];
        x[i] = v; s += v; qq += v * v;
    }
    #pragma unroll
    for (int o = 16; o; o >>= 1) {
        s  += __shfl_xor_sync(0xffffffffu, s, o);
        qq += __shfl_xor_sync(0xffffffffu, qq, o);
    }
    float mu = s * (1.f / 256.f);
    float var = fmaxf(qq * (1.f / 256.f) - mu * mu, 0.f);
    float inv = rsqrtf(var + 1e-5f);
    #pragma unroll
    for (int i = 0; i < 8; i++) {
        int d = lane + (i << 5);
        float y = (x[i] - mu) * inv * lg[d] + lb[d];
        Hr[base + d] = y;
        __half hb, lbv;
        hsplit(y, hb, lbv);
        Hh[base + d] = hb;
        Hl[base + d] = lbv;
    }
}

// ---------------------------------------------------------------------------
// both bias vectors in one launch: grid (MR/8, 2)
// ---------------------------------------------------------------------------
__global__ void __launch_bounds__(256) biasvec2_k(
    const float* __restrict__ X0, const float* __restrict__ w0, const float* __restrict__ c0,
    const float* __restrict__ X1, const float* __restrict__ w1, const float* __restrict__ c1,
    float* __restrict__ o0, float* __restrict__ o1)
{
    int sel = blockIdx.y;
    const float* X = sel ? X1 : X0;
    const float* w = sel ? w1 : w0;
    const float* cb = sel ? c1 : c0;
    float* out = sel ? o1 : o0;
    int row  = blockIdx.x * 8 + (threadIdx.x >> 5);
    int lane = threadIdx.x & 31;
    const float* x = X + (size_t)row * 256;
    float s = 0.f;
    for (int d = lane; d < 256; d += 32) s += x[d] * w[d];
    #pragma unroll
    for (int o = 16; o; o >>= 1) s += __shfl_xor_sync(0xffffffffu, s, o);
    if (lane == 0) out[row] = s + cb[0];
}

// ---------------------------------------------------------------------------
// Final scores (fp32 f32x2 path)
// ---------------------------------------------------------------------------
__device__ __forceinline__ void unpk(unsigned long long p, float& x, float& y) {
    asm("mov.b64 {%0, %1}, %2;" : "=f"(x), "=f"(y) : "l"(p));
}
#define SSM_BYTES ((16*132 * 2) * 4)

__global__ void __launch_bounds__(256, 2) scores2_k(
    const float* __restrict__ T, const float* __restrict__ Hd,
    const float* __restrict__ bh, const float* __restrict__ bd,
    float* __restrict__ S)
{
    extern __shared__ float smx2[];
    float* As = smx2;
    float* Bs = smx2 + 16 * 132;
    const int b = blockIdx.x;
    const int tid = threadIdx.x;
    const int tr = tid >> 4, tc = tid & 15;
    const int ra = tid >> 2, ca = (tid & 3) << 2;
    const float* Ab = T  + (size_t)b * NN * DM;
    const float* Bb = Hd + (size_t)b * NN * DM;

    unsigned long long acc[8][4];
    #pragma unroll
    for (int i = 0; i < 8; i++)
        #pragma unroll
        for (int j = 0; j < 4; j++) acc[i][j] = 0ull;

    float4 a0, a1, b0, b1;
    a0 = *(const float4*)(Ab + (size_t)ra * 256 + ca);
    a1 = *(const float4*)(Ab + (size_t)(ra + 64) * 256 + ca);
    b0 = *(const float4*)(Bb + (size_t)ra * 256 + ca);
    b1 = *(const float4*)(Bb + (size_t)(ra + 64) * 256 + ca);

    for (int kt = 0; kt < 256; kt += 16) {
        __syncthreads();
        As[(ca+0)*132 + ra] = a0.x; As[(ca+1)*132 + ra] = a0.y;
        As[(ca+2)*132 + ra] = a0.z; As[(ca+3)*132 + ra] = a0.w;
        As[(ca+0)*132 + ra + 64] = a1.x; As[(ca+1)*132 + ra + 64] = a1.y;
        As[(ca+2)*132 + ra + 64] = a1.z; As[(ca+3)*132 + ra + 64] = a1.w;
        Bs[(ca+0)*132 + ra] = b0.x; Bs[(ca+1)*132 + ra] = b0.y;
        Bs[(ca+2)*132 + ra] = b0.z; Bs[(ca+3)*132 + ra] = b0.w;
        Bs[(ca+0)*132 + ra + 64] = b1.x; Bs[(ca+1)*132 + ra + 64] = b1.y;
        Bs[(ca+2)*132 + ra + 64] = b1.z; Bs[(ca+3)*132 + ra + 64] = b1.w;
        __syncthreads();
        if (kt + 16 < 256) {
            a0 = *(const float4*)(Ab + (size_t)ra * 256 + kt + 16 + ca);
            a1 = *(const float4*)(Ab + (size_t)(ra + 64) * 256 + kt + 16 + ca);
            b0 = *(const float4*)(Bb + (size_t)ra * 256 + kt + 16 + ca);
            b1 = *(const float4*)(Bb + (size_t)(ra + 64) * 256 + kt + 16 + ca);
        }
        #pragma unroll
        for (int kk = 0; kk < 16; kk++) {
            float4 av0 = *(const float4*)&As[kk*132 + (tr << 2)];
            float4 av1 = *(const float4*)&As[kk*132 + 64 + (tr << 2)];
            ulonglong2 bq0 = *(const ulonglong2*)&Bs[kk*132 + (tc << 2)];
            ulonglong2 bq1 = *(const ulonglong2*)&Bs[kk*132 + 64 + (tc << 2)];
            float a_[8] = {av0.x, av0.y, av0.z, av0.w, av1.x, av1.y, av1.z, av1.w};
            #pragma unroll
            for (int i = 0; i < 8; i++) {
                unsigned long long ap;
                asm("mov.b64 %0, {%1, %1};" : "=l"(ap) : "f"(a_[i]));
                asm("fma.rn.f32x2 %0, %1, %2, %0;" : "+l"(acc[i][0]) : "l"(ap), "l"(bq0.x));
                asm("fma.rn.f32x2 %0, %1, %2, %0;" : "+l"(acc[i][1]) : "l"(ap), "l"(bq0.y));
                asm("fma.rn.f32x2 %0, %1, %2, %0;" : "+l"(acc[i][2]) : "l"(ap), "l"(bq1.x));
                asm("fma.rn.f32x2 %0, %1, %2, %0;" : "+l"(acc[i][3]) : "l"(ap), "l"(bq1.y));
            }
        }
    }

    float cb[8];
    #pragma unroll
    for (int j = 0; j < 8; j++) {
        int c = (j < 4) ? ((tc << 2) + j) : (64 + (tc << 2) + j - 4);
        cb[j] = bh[b * NN + c];
    }
    #pragma unroll
    for (int i = 0; i < 8; i++) {
        int n = (i < 4) ? ((tr << 2) + i) : (64 + (tr << 2) + i - 4);
        float rb = bd[b * NN + n];
        float o[8];
        unpk(acc[i][0], o[0], o[1]); unpk(acc[i][1], o[2], o[3]);
        unpk(acc[i][2], o[4], o[5]); unpk(acc[i][3], o[6], o[7]);
        float4 s0 = {o[0]+rb+cb[0], o[1]+rb+cb[1], o[2]+rb+cb[2], o[3]+rb+cb[3]};
        float4 s1 = {o[4]+rb+cb[4], o[5]+rb+cb[5], o[6]+rb+cb[6], o[7]+rb+cb[7]};
        *(float4*)(S + (size_t)b * NN * NN + (size_t)n * NN + (tc << 2))      = s0;
        *(float4*)(S + (size_t)b * NN * NN + (size_t)n * NN + 64 + (tc << 2)) = s1;
    }
}

// ---------------------------------------------------------------------------
// Host orchestration
// ---------------------------------------------------------------------------
extern "C" void kernel_launch(void* const* d_in, const int* in_sizes, int n_in,
                              void* d_out, int out_size)
{
    const float* Hin    = (const float*)d_in[0];
    const int*   ph     = (const int*)  d_in[1];
    const float* mask   = (const float*)d_in[2];
    const float* ha_w   = (const float*)d_in[3];
    const float* ha_b   = (const float*)d_in[4];
    const float* sa_w   = (const float*)d_in[5];
    const float* sa_b   = (const float*)d_in[6];
    const float* ct_w   = (const float*)d_in[7];
    const float* ct_b   = (const float*)d_in[8];
    const float* gate_w = (const float*)d_in[9];
    const float* gate_b = (const float*)d_in[10];
    const float* tr_w   = (const float*)d_in[11];
    const float* tr_b   = (const float*)d_in[12];
    const float* ln_g   = (const float*)d_in[13];
    const float* ln_b   = (const float*)d_in[14];
    const float* ahw    = (const float*)d_in[15];
    const float* ahb    = (const float*)d_in[16];
    const float* adw    = (const float*)d_in[17];
    const float* adb    = (const float*)d_in[18];
    const float* bil    = (const float*)d_in[19];
    const float* bhw    = (const float*)d_in[20];
    const float* bhb    = (const float*)d_in[21];
    const float* bdw    = (const float*)d_in[22];
    const float* bdb    = (const float*)d_in[23];

    float* Hr     = (float*)d_out;
    float* scores = Hr + (size_t)MR * DM;

    float *qf_, *kf_, *vf_, *ga_, *tu_, *bt_, *aq_, *ad_, *bhv_, *bdv_;
    __half *hrh, *hrl, *ath, *atl, *hmh, *hml, *cmh, *cml, *sbh, *sbl,
           *cvh, *cvl, *qah, *qal, *whi_, *wlo_;
    cudaGetSymbolAddress((void**)&qf_, g_q);
    cudaGetSymbolAddress((void**)&kf_, g_k);
    cudaGetSymbolAddress((void**)&vf_, g_v);
    cudaGetSymbolAddress((void**)&ga_, g_gate);
    cudaGetSymbolAddress((void**)&tu_, g_tr);
    cudaGetSymbolAddress((void**)&bt_, g_bil);
    cudaGetSymbolAddress((void**)&aq_, g_arcq);
    cudaGetSymbolAddress((void**)&ad_, g_arcd);
    cudaGetSymbolAddress((void**)&bhv_, g_bh);
    cudaGetSymbolAddress((void**)&bdv_, g_bd);
    cudaGetSymbolAddress((void**)&hrh, g_hr_h);  cudaGetSymbolAddress((void**)&hrl, g_hr_l);
    cudaGetSymbolAddress((void**)&ath, g_at_h);  cudaGetSymbolAddress((void**)&atl, g_at_l);
    cudaGetSymbolAddress((void**)&hmh, g_hm_h);  cudaGetSymbolAddress((void**)&hml, g_hm_l);
    cudaGetSymbolAddress((void**)&cmh, g_cm_h);  cudaGetSymbolAddress((void**)&cml, g_cm_l);
    cudaGetSymbolAddress((void**)&sbh, g_sb_h);  cudaGetSymbolAddress((void**)&sbl, g_sb_l);
    cudaGetSymbolAddress((void**)&cvh, g_cav_h); cudaGetSymbolAddress((void**)&cvl, g_cav_l);
    cudaGetSymbolAddress((void**)&qah, g_qa_h);  cudaGetSymbolAddress((void**)&qal, g_qa_l);
    cudaGetSymbolAddress((void**)&whi_, g_whi);  cudaGetSymbolAddress((void**)&wlo_, g_wlo);

    // half plane views: hi plane then lo plane inside each fp32 scratch array
    __half* hQh = (__half*)qf_; __half* hQl = hQh + (size_t)MR * DM;
    __half* hKh = (__half*)kf_; __half* hKl = hKh + (size_t)MR * DM;
    __half* hVh = (__half*)vf_; __half* hVl = hVh + (size_t)MR * DM;
    __half* sQh = (__half*)ga_; __half* sQl = sQh + (size_t)MR * DM;
    __half* sKh = (__half*)tu_; __half* sKl = sKh + (size_t)MR * DM;
    __half* sVh = (__half*)bt_; __half* sVl = sVh + (size_t)MR * DM;

    cudaFuncSetAttribute(mg1_k,     cudaFuncAttributeMaxDynamicSharedMemorySize, MG_SMEM);
    cudaFuncSetAttribute(mg_qkv2_k, cudaFuncAttributeMaxDynamicSharedMemorySize, MG_SMEM);
    cudaFuncSetAttribute(proj3_k,   cudaFuncAttributeMaxDynamicSharedMemorySize, MG_SMEM);
    cudaFuncSetAttribute(mg_gt_k,   cudaFuncAttributeMaxDynamicSharedMemorySize, MG_SMEM);
    cudaFuncSetAttribute(mg_arc_k,  cudaFuncAttributeMaxDynamicSharedMemorySize, MG_SMEM);
    cudaFuncSetAttribute(attnB_k,   cudaFuncAttributeMaxDynamicSharedMemorySize, ATC_SMEM);
    cudaFuncSetAttribute(child_k,   cudaFuncAttributeMaxDynamicSharedMemorySize, CHILD_SMEM);

    wconv_k<<<dim3(8, 32, 36), dim3(32, 8)>>>(ha_w, sa_w, ct_w, gate_w, tr_w, ahw, adw, bil);
    split_k<<<MR * DM / 1024, 256>>>(Hin, Hr, hrh, hrl);

    for (int i = 0; i < 3; i++) {
        const __half* hwh = whi_ + WOFF_HA + (size_t)i * 4 * 65536;
        const __half* hwl = wlo_ + WOFF_HA + (size_t)i * 4 * 65536;
        const __half* swh = whi_ + WOFF_SA + (size_t)i * 4 * 65536;
        const __half* swl = wlo_ + WOFF_SA + (size_t)i * 4 * 65536;
        const float*  hb  = ha_b + (size_t)i * 1024;
        const float*  sbb = sa_b + (size_t)i * 1024;

        // both QKV sets in one launch (1-term fp16)
        mg_qkv2_k<<<dim3(256, 12), 256, MG_SMEM>>>(hrh, hrl, hwh, hwl, hb, swh, swl, sbb,
                                                   hQh, hQl, hKh, hKl, hVh, hVl,
                                                   sQh, sQl, sKh, sKl, sVh, sVl);
        // child scatter-mean (independent)
        child_k<<<dim3(256, 2), 128, CHILD_SMEM>>>(Hr, ph, mask, cvh, cvl);
        // both attentions in one launch (3-term internals)
        attnB_k<<<dim3(BB, NHH, 2), 256, ATC_SMEM>>>(hQh, hQl, hKh, hKl, hVh, hVl,
                                                     sQh, sQl, sKh, sKl, sVh, sVl,
                                                     ph, mask, ath, atl, qah, qal);
        // head proj + sib proj + child MLP in one launch (1-term fp16)
        proj3_k<<<dim3(256, 6), 256, MG_SMEM>>>(ath, atl, qah, qal, hrh, hrl, cvh, cvl,
                                                hwh + 3*65536, hwl + 3*65536, hb + 768,
                                                swh + 3*65536, swl + 3*65536, sbb + 768,
                                                whi_ + WOFF_CT + (size_t)i * 131072,
                                                wlo_ + WOFF_CT + (size_t)i * 131072,
                                                ct_b + (size_t)i * 256,
                                                hmh, hml, sbh, sbl, cmh, cml);
        // gated fuse (1-term fp16)
        mg_gt_k<<<dim3(256, 4), 256, MG_SMEM>>>(hrh, hrl, hmh, hml, cmh, cml, sbh, sbl,
                                                whi_ + WOFF_GATE + (size_t)i * 262144,
                                                wlo_ + WOFF_GATE + (size_t)i * 262144,
                                                whi_ + WOFF_TR + (size_t)i * 262144,
                                                wlo_ + WOFF_TR + (size_t)i * 262144,
                                                gate_b + (size_t)i * 256,
                                                tr_b   + (size_t)i * 256, ga_, tu_);
        fuse_ln_k<<<MR / 8, 256>>>(Hr, ga_, tu_, ln_g + (size_t)i * 256,
                                   ln_b + (size_t)i * 256, hrh, hrl);
    }

    // final biaffine scorer (3-term: feeds scores output directly)
    mg_arc_k<<<dim3(256, 4), 256, MG_SMEM>>>(hrh, hrl,
                                             whi_ + WOFF_ARCH, wlo_ + WOFF_ARCH, ahb,
                                             whi_ + WOFF_ARCD, wlo_ + WOFF_ARCD, adb,
                                             aq_, qah, qal, ad_);
    mg1_k<<<dim3(256, 2), 256, MG_SMEM>>>(qah, qal, whi_ + WOFF_BIL, wlo_ + WOFF_BIL,
                                          nullptr, bt_, nullptr, nullptr, 0, 1);
    biasvec2_k<<<dim3(MR / 8, 2), 256>>>(aq_, bhw, bhb, ad_, bdw, bdb, bhv_, bdv_);
    scores2_k<<<BB, 256, SSM_BYTES>>>(bt_, ad_, bhv_, bdv_, scores);
}